// round 7
// baseline (speedup 1.0000x reference)
#include <cuda_runtime.h>
#include <cuda_bf16.h>
#include <math.h>
#include <stdint.h>

// Problem constants
#define Dd 32
#define Hh 1024
#define Ll 2
#define Bb 4096

typedef __nv_bfloat16 bf16;

// ---------------- device scratch (static, no allocation) ----------------
__device__ float g_pre0[Bb * Hh];       // layer-0 pre-activations (fp32, incremental)
__device__ bf16  g_p0hi[Bb * Hh];       // split(relu(pre0)) hi
__device__ bf16  g_p0lo[Bb * Hh];       // split(relu(pre0)) lo
__device__ bf16  g_a1hi[Bb * Hh];       // layer-1 activation split hi
__device__ bf16  g_a1lo[Bb * Hh];       // layer-1 activation split lo
__device__ float g_a2[Bb * Hh];         // layer-2 activation (fp32, post-relu)
__device__ bf16  g_Wh_hi[Ll * Hh * Hh]; // masked+sorted hidden weights, bf16 hi
__device__ bf16  g_Wh_lo[Ll * Hh * Hh]; // bf16 lo residual
__device__ float g_bhs[Ll * Hh];        // permuted hidden biases
__device__ float g_W0sT[Dd * Hh];       // masked, sorted W0, transposed [D][H]
__device__ float g_Wos[2 * Dd * Hh];    // masked output weights, sorted cols

// Degree-sorted permutation. Hidden degree of original unit i is i % 31.
__device__ __forceinline__ int permS(int s) {
    return (s < 34) ? 31 * s : ((s - 1) / 33) + 31 * ((s - 1) % 33);
}
__device__ __forceinline__ int degS(int s) {
    return (s < 34) ? 0 : (s - 1) / 33;
}
static inline int prefixH(int idx) { return (idx == 0) ? 0 : (33 * idx + 1); }

// ---------------- weight pre-transform + state init (merged) ----------------
__global__ void prep_kernel(const float* __restrict__ W0,
                            const float* __restrict__ b0,
                            const float* __restrict__ Wh,
                            const float* __restrict__ bh,
                            const float* __restrict__ Wout) {
    int stride = gridDim.x * blockDim.x;
    int tid0 = blockIdx.x * blockDim.x + threadIdx.x;

    for (int i = tid0; i < Ll * Hh * Hh; i += stride) {
        int l = i >> 20;
        int rem = i & (Hh * Hh - 1);
        int s = rem >> 10;
        int t = rem & (Hh - 1);
        float v = 0.f;
        if (degS(s) >= degS(t)) v = Wh[l * Hh * Hh + permS(s) * Hh + permS(t)];
        bf16 hi = __float2bfloat16_rn(v);
        g_Wh_hi[i] = hi;
        g_Wh_lo[i] = __float2bfloat16_rn(v - __bfloat162float(hi));
    }
    for (int i = tid0; i < Ll * Hh; i += stride) {
        int l = i >> 10;
        int s = i & (Hh - 1);
        g_bhs[i] = bh[l * Hh + permS(s)];
    }
    for (int i = tid0; i < Dd * Hh; i += stride) {
        int j = i >> 10;
        int s = i & (Hh - 1);
        g_W0sT[i] = (degS(s) >= j) ? W0[permS(s) * Dd + j] : 0.f;
    }
    for (int i = tid0; i < 2 * Dd * Hh; i += stride) {
        int o = i >> 10;
        int t = i & (Hh - 1);
        g_Wos[i] = (((o & 31) - 1) >= degS(t)) ? Wout[o * Hh + permS(t)] : 0.f;
    }
    // state init
    for (int i = tid0; i < Bb * Hh; i += stride) {
        int s = i & (Hh - 1);
        float v = b0[permS(s)];
        g_pre0[i] = v;
        float y = fmaxf(v, 0.f);
        bf16 hi = __float2bfloat16_rn(y);
        g_p0hi[i] = hi;
        g_p0lo[i] = __float2bfloat16_rn(y - __bfloat162float(hi));
        g_a1hi[i] = __float2bfloat16_rn(0.f);
        g_a1lo[i] = __float2bfloat16_rn(0.f);
        g_a2[i] = 0.f;
    }
}

// ---------------- bf16 TC GEMM, 3-pass compensated, 128x128 tile ----------------
#define BM 128
#define BN 128
#define BK 32
#define APAD 40   // bf16 per smem row (80B) -> conflict-free ldmatrix

#define SM_AH 0
#define SM_AL (BM * APAD)
#define SM_BH (2 * BM * APAD)
#define SM_BL (2 * BM * APAD + BN * APAD)
#define SM_STAGE (2 * BM * APAD + 2 * BN * APAD)   // 20480 bf16 per stage
#define SMEM_BYTES (2 * SM_STAGE * 2)              // 81920 bytes

__device__ __forceinline__ uint32_t smem_u32(const void* p) {
    return (uint32_t)__cvta_generic_to_shared(p);
}
__device__ __forceinline__ void cp16(uint32_t dst, const void* src) {
    asm volatile("cp.async.cg.shared.global [%0], [%1], 16;\n" :: "r"(dst), "l"(src));
}
__device__ __forceinline__ void cp_commit() {
    asm volatile("cp.async.commit_group;\n");
}
__device__ __forceinline__ void cp_wait1() {
    asm volatile("cp.async.wait_group 1;\n");
}
__device__ __forceinline__ void ldsm4(uint32_t& r0, uint32_t& r1, uint32_t& r2,
                                      uint32_t& r3, uint32_t addr) {
    asm volatile("ldmatrix.sync.aligned.m8n8.x4.shared.b16 {%0,%1,%2,%3}, [%4];\n"
                 : "=r"(r0), "=r"(r1), "=r"(r2), "=r"(r3) : "r"(addr));
}
__device__ __forceinline__ void mma_bf16(float c[4], const uint32_t a[4], const uint32_t b[2]) {
    asm volatile(
        "mma.sync.aligned.m16n8k16.row.col.f32.bf16.bf16.f32 "
        "{%0,%1,%2,%3}, {%4,%5,%6,%7}, {%8,%9}, {%0,%1,%2,%3};\n"
        : "+f"(c[0]), "+f"(c[1]), "+f"(c[2]), "+f"(c[3])
        : "r"(a[0]), "r"(a[1]), "r"(a[2]), "r"(a[3]), "r"(b[0]), "r"(b[1]));
}

// OUTMODE 0: write fp32 (relu). OUTMODE 1: write bf16 split hi/lo (relu).
template <int OUTMODE>
__global__ __launch_bounds__(256, 2) void gemm_tc(const bf16* __restrict__ Ahi,
                                                  const bf16* __restrict__ Alo,
                                                  const bf16* __restrict__ Whi,
                                                  const bf16* __restrict__ Wlo,
                                                  const float* __restrict__ bias,
                                                  float* __restrict__ outF,
                                                  bf16* __restrict__ outHi,
                                                  bf16* __restrict__ outLo,
                                                  int h, int nj) {
    extern __shared__ bf16 sm[];

    const int m0 = blockIdx.x * BM;
    const int jb = nj - 1 - (int)blockIdx.y;   // heavy-K tiles first
    const int n0 = jb * BN;

    // triangular K-limit for this N-tile
    int s1 = min(n0 + BN - 1, h - 1);
    int g1 = (s1 < 34) ? 0 : (s1 - 1) / 33;
    int kmax = min(h, 33 * g1 + 34);
    kmax = (kmax + BK - 1) & ~(BK - 1);
    const int nIter = kmax / BK;

    const int tid = (int)threadIdx.x;
    const int lane = tid & 31;
    const int wid = tid >> 5;
    const int wm = wid & 1;        // warp M (0..1), 64 rows each
    const int wn = wid >> 1;       // warp N (0..3), 32 cols each
    const int g = lane >> 2;
    const int tg = lane & 3;

    // staging: A hi/lo and B hi/lo each 128 rows x 4 16B-chunks = 1024 slots
    auto prefetch = [&](int stage, int k0) {
        uint32_t sbase = smem_u32(sm) + (uint32_t)(stage * SM_STAGE) * 2u;
#pragma unroll
        for (int i = 0; i < 4; i++) {
            int idx = tid + i * 256;
            int half = idx >> 9;
            int r = (idx & 511) >> 2;
            int ch = idx & 3;
            const bf16* src = (half ? Alo : Ahi) + (size_t)(m0 + r) * Hh + k0 + ch * 8;
            uint32_t dst = sbase + (uint32_t)((half ? SM_AL : SM_AH) + r * APAD + ch * 8) * 2u;
            cp16(dst, src);
        }
#pragma unroll
        for (int i = 0; i < 4; i++) {
            int idx = tid + i * 256;
            int half = idx >> 9;
            int r = (idx & 511) >> 2;
            int ch = idx & 3;
            const bf16* src = (half ? Wlo : Whi) + (size_t)(n0 + r) * Hh + k0 + ch * 8;
            uint32_t dst = sbase + (uint32_t)((half ? SM_BL : SM_BH) + r * APAD + ch * 8) * 2u;
            cp16(dst, src);
        }
    };

    float c[4][4][4];
#pragma unroll
    for (int mi = 0; mi < 4; mi++)
#pragma unroll
        for (int ni = 0; ni < 4; ni++)
#pragma unroll
            for (int q = 0; q < 4; q++) c[mi][ni][q] = 0.f;

    const int lrow = lane & 15;
    const int lkof = (lane >> 4) << 3;

    prefetch(0, 0);
    cp_commit();

    for (int it = 0; it < nIter; it++) {
        const int buf = it & 1;
        if (it + 1 < nIter) prefetch(buf ^ 1, (it + 1) * BK);
        cp_commit();
        cp_wait1();
        __syncthreads();

        uint32_t sbase = smem_u32(sm) + (uint32_t)(buf * SM_STAGE) * 2u;
        const uint32_t sAhi = sbase;
        const uint32_t sAlo = sbase + (uint32_t)SM_AL * 2u;
        const uint32_t sBhi = sbase + (uint32_t)SM_BH * 2u;
        const uint32_t sBlo = sbase + (uint32_t)SM_BL * 2u;

#pragma unroll
        for (int kst = 0; kst < 2; kst++) {
            const int ks = kst * 16;
            uint32_t ah[4][4], al[4][4];
#pragma unroll
            for (int mi = 0; mi < 4; mi++) {
                int row = wm * 64 + mi * 16 + lrow;
                uint32_t off = (uint32_t)(row * APAD + ks + lkof) * 2u;
                ldsm4(ah[mi][0], ah[mi][1], ah[mi][2], ah[mi][3], sAhi + off);
                ldsm4(al[mi][0], al[mi][1], al[mi][2], al[mi][3], sAlo + off);
            }
            uint32_t bh[4][2], bl[4][2];
#pragma unroll
            for (int nj2 = 0; nj2 < 2; nj2++) {
                int nrow = wn * 32 + nj2 * 16 + lrow;
                uint32_t off = (uint32_t)(nrow * APAD + ks + lkof) * 2u;
                uint32_t t0, t1, t2, t3;
                ldsm4(t0, t1, t2, t3, sBhi + off);
                bh[nj2 * 2][0] = t0; bh[nj2 * 2 + 1][0] = t1;
                bh[nj2 * 2][1] = t2; bh[nj2 * 2 + 1][1] = t3;
                ldsm4(t0, t1, t2, t3, sBlo + off);
                bl[nj2 * 2][0] = t0; bl[nj2 * 2 + 1][0] = t1;
                bl[nj2 * 2][1] = t2; bl[nj2 * 2 + 1][1] = t3;
            }
#pragma unroll
            for (int mi = 0; mi < 4; mi++)
#pragma unroll
                for (int ni = 0; ni < 4; ni++) {
                    mma_bf16(c[mi][ni], ah[mi], bh[ni]);
                    mma_bf16(c[mi][ni], al[mi], bh[ni]);
                    mma_bf16(c[mi][ni], ah[mi], bl[ni]);
                }
        }
        __syncthreads();
    }

    // ---- epilogue: bias + relu, store cols < h ----
#pragma unroll
    for (int mi = 0; mi < 4; mi++) {
        int r0 = m0 + wm * 64 + mi * 16 + g;
#pragma unroll
        for (int ni = 0; ni < 4; ni++) {
            int col = n0 + wn * 32 + ni * 8 + tg * 2;
#pragma unroll
            for (int q = 0; q < 2; q++) {
                int cc = col + q;
                if (cc < h) {
                    float bv = bias[cc];
                    float y0 = fmaxf(c[mi][ni][q] + bv, 0.f);
                    float y1 = fmaxf(c[mi][ni][q + 2] + bv, 0.f);
                    if (OUTMODE == 0) {
                        outF[(size_t)r0 * Hh + cc] = y0;
                        outF[(size_t)(r0 + 8) * Hh + cc] = y1;
                    } else {
                        bf16 h0 = __float2bfloat16_rn(y0);
                        bf16 h1 = __float2bfloat16_rn(y1);
                        outHi[(size_t)r0 * Hh + cc] = h0;
                        outHi[(size_t)(r0 + 8) * Hh + cc] = h1;
                        outLo[(size_t)r0 * Hh + cc] =
                            __float2bfloat16_rn(y0 - __bfloat162float(h0));
                        outLo[(size_t)(r0 + 8) * Hh + cc] =
                            __float2bfloat16_rn(y1 - __bfloat162float(h1));
                    }
                }
            }
        }
    }
}

// ---------------- fused output + state update per step ----------------
__global__ __launch_bounds__(128) void finish_kernel(const float* __restrict__ z,
                                                     const float* __restrict__ bout,
                                                     float* __restrict__ x,
                                                     int idx, int h) {
    int r = blockIdx.x;
    int t = (int)threadIdx.x;
    const float* arow = g_a2 + (size_t)r * Hh;
    const float* wmu = g_Wos + (size_t)idx * Hh;
    const float* wls = g_Wos + (size_t)(idx + Dd) * Hh;

    float smu = 0.f, sls = 0.f;
    for (int ccol = t; ccol < h; ccol += 128) {
        float av = arow[ccol];
        smu += av * wmu[ccol];
        sls += av * wls[ccol];
    }
#pragma unroll
    for (int off = 16; off; off >>= 1) {
        smu += __shfl_down_sync(0xffffffffu, smu, off);
        sls += __shfl_down_sync(0xffffffffu, sls, off);
    }
    __shared__ float rmu[4], rls[4];
    __shared__ float s_xi;
    if ((t & 31) == 0) { rmu[t >> 5] = smu; rls[t >> 5] = sls; }
    __syncthreads();
    if (t == 0) {
        float mu = rmu[0] + rmu[1] + rmu[2] + rmu[3] + bout[idx];
        float ls = rls[0] + rls[1] + rls[2] + rls[3] + bout[idx + Dd];
        float xi = z[(size_t)r * Dd + idx] * expf(ls) + mu;
        x[(size_t)r * Dd + idx] = xi;
        s_xi = xi;
    }
    __syncthreads();
    float xi = s_xi;
    const float* w0col = g_W0sT + idx * Hh;
    float* prow = g_pre0 + (size_t)r * Hh;
    bf16* phrow = g_p0hi + (size_t)r * Hh;
    bf16* plrow = g_p0lo + (size_t)r * Hh;
    for (int s = h + t; s < Hh; s += 128) {
        float v = prow[s] + w0col[s] * xi;
        prow[s] = v;
        float y = fmaxf(v, 0.f);
        bf16 hi = __float2bfloat16_rn(y);
        phrow[s] = hi;
        plrow[s] = __float2bfloat16_rn(y - __bfloat162float(hi));
    }
}

// ---------------- launch ----------------
extern "C" void kernel_launch(void* const* d_in, const int* in_sizes, int n_in,
                              void* d_out, int out_size) {
    const float* z    = (const float*)d_in[0];
    const float* W0   = (const float*)d_in[1];
    const float* b0   = (const float*)d_in[2];
    const float* Wh   = (const float*)d_in[3];
    const float* bh   = (const float*)d_in[4];
    const float* Wout = (const float*)d_in[5];
    const float* bout = (const float*)d_in[6];
    float* x = (float*)d_out;

    static int attrSet = 0;
    if (!attrSet) {
        cudaFuncSetAttribute(gemm_tc<0>, cudaFuncAttributeMaxDynamicSharedMemorySize, SMEM_BYTES);
        cudaFuncSetAttribute(gemm_tc<1>, cudaFuncAttributeMaxDynamicSharedMemorySize, SMEM_BYTES);
        attrSet = 1;
    }

    prep_kernel<<<1024, 256>>>(W0, b0, Wh, bh, Wout);

    float *a2, *bhs;
    bf16 *p0hi, *p0lo, *a1hi, *a1lo, *Whi, *Wlo;
    cudaGetSymbolAddress((void**)&p0hi, g_p0hi);
    cudaGetSymbolAddress((void**)&p0lo, g_p0lo);
    cudaGetSymbolAddress((void**)&a1hi, g_a1hi);
    cudaGetSymbolAddress((void**)&a1lo, g_a1lo);
    cudaGetSymbolAddress((void**)&a2, g_a2);
    cudaGetSymbolAddress((void**)&Whi, g_Wh_hi);
    cudaGetSymbolAddress((void**)&Wlo, g_Wh_lo);
    cudaGetSymbolAddress((void**)&bhs, g_bhs);

    for (int idx = 0; idx < Dd; idx++) {
        int h = prefixH(idx);
        if (h > 0) {
            int nj = (h + BN - 1) >> 7;
            dim3 grid(Bb / BM, nj);
            gemm_tc<1><<<grid, 256, SMEM_BYTES>>>(p0hi, p0lo, Whi, Wlo, bhs,
                                                  nullptr, a1hi, a1lo, h, nj);
            gemm_tc<0><<<grid, 256, SMEM_BYTES>>>(a1hi, a1lo, Whi + Hh * Hh,
                                                  Wlo + Hh * Hh, bhs + Hh, a2,
                                                  nullptr, nullptr, h, nj);
        }
        finish_kernel<<<Bb, 128>>>(z, bout, x, idx, h);
    }
}

// round 8
// speedup vs baseline: 2.3038x; 2.3038x over previous
#include <cuda_runtime.h>
#include <cuda_bf16.h>
#include <math.h>
#include <stdint.h>

// Problem constants
#define Dd 32
#define Hh 1024
#define Ll 2
#define Bb 4096
#define BMs 32
#define NCTA (Bb / BMs)   // 128 CTAs, each owns 32 batch rows for the whole run

typedef __nv_bfloat16 bf16;

// ---------------- device scratch (static, no allocation) ----------------
__device__ float g_pre0[Bb * Hh];
__device__ bf16  g_p0hi[Bb * Hh];
__device__ bf16  g_p0lo[Bb * Hh];
__device__ bf16  g_a1hi[Bb * Hh];
__device__ bf16  g_a1lo[Bb * Hh];
__device__ float g_a2[Bb * Hh];
__device__ bf16  g_Wh_hi[Ll * Hh * Hh];
__device__ bf16  g_Wh_lo[Ll * Hh * Hh];
__device__ float g_bhs[Ll * Hh];
__device__ float g_W0sT[Dd * Hh];
__device__ float g_Wos[2 * Dd * Hh];

// Degree-sorted permutation. Hidden degree of original unit i is i % 31.
__device__ __forceinline__ int permS(int s) {
    return (s < 34) ? 31 * s : ((s - 1) / 33) + 31 * ((s - 1) % 33);
}
__device__ __forceinline__ int degS(int s) {
    return (s < 34) ? 0 : (s - 1) / 33;
}

// ---------------- weight pre-transform + state init ----------------
__global__ void prep_kernel(const float* __restrict__ W0,
                            const float* __restrict__ b0,
                            const float* __restrict__ Wh,
                            const float* __restrict__ bh,
                            const float* __restrict__ Wout) {
    int stride = gridDim.x * blockDim.x;
    int tid0 = blockIdx.x * blockDim.x + threadIdx.x;

    for (int i = tid0; i < Ll * Hh * Hh; i += stride) {
        int l = i >> 20;
        int rem = i & (Hh * Hh - 1);
        int s = rem >> 10;
        int t = rem & (Hh - 1);
        float v = 0.f;
        if (degS(s) >= degS(t)) v = Wh[l * Hh * Hh + permS(s) * Hh + permS(t)];
        bf16 hi = __float2bfloat16_rn(v);
        g_Wh_hi[i] = hi;
        g_Wh_lo[i] = __float2bfloat16_rn(v - __bfloat162float(hi));
    }
    for (int i = tid0; i < Ll * Hh; i += stride) {
        int l = i >> 10;
        int s = i & (Hh - 1);
        g_bhs[i] = bh[l * Hh + permS(s)];
    }
    for (int i = tid0; i < Dd * Hh; i += stride) {
        int j = i >> 10;
        int s = i & (Hh - 1);
        g_W0sT[i] = (degS(s) >= j) ? W0[permS(s) * Dd + j] : 0.f;
    }
    for (int i = tid0; i < 2 * Dd * Hh; i += stride) {
        int o = i >> 10;
        int t = i & (Hh - 1);
        g_Wos[i] = (((o & 31) - 1) >= degS(t)) ? Wout[o * Hh + permS(t)] : 0.f;
    }
    for (int i = tid0; i < Bb * Hh; i += stride) {
        int s = i & (Hh - 1);
        float v = b0[permS(s)];
        g_pre0[i] = v;
        float y = fmaxf(v, 0.f);
        bf16 hi = __float2bfloat16_rn(y);
        g_p0hi[i] = hi;
        g_p0lo[i] = __float2bfloat16_rn(y - __bfloat162float(hi));
    }
}

// ---------------- smem layout (dynamic, bytes) ----------------
// stage s (s=0,1) at s*15360:
//   Ahi [32][40] bf16 @0, Alo @2560, Bhi [64][40] @5120, Blo @10240
// a1 window (2 K-chunks) hi @30720, lo @35840 : [2][32][40] bf16 each
// a2 window fp32 [32][65] @40960
#define STG_BYTES 15360
#define A1W_HI 30720
#define A1W_LO 35840
#define A2W_OFF 40960
#define SMEMB 49280

__device__ __forceinline__ uint32_t smem_u32(const void* p) {
    return (uint32_t)__cvta_generic_to_shared(p);
}
__device__ __forceinline__ void cp16(uint32_t dst, const void* src) {
    asm volatile("cp.async.cg.shared.global [%0], [%1], 16;\n" :: "r"(dst), "l"(src));
}
__device__ __forceinline__ void cp_commit() { asm volatile("cp.async.commit_group;\n"); }
__device__ __forceinline__ void cp_wait1() { asm volatile("cp.async.wait_group 1;\n"); }
__device__ __forceinline__ void ldsm4(uint32_t& r0, uint32_t& r1, uint32_t& r2,
                                      uint32_t& r3, uint32_t addr) {
    asm volatile("ldmatrix.sync.aligned.m8n8.x4.shared.b16 {%0,%1,%2,%3}, [%4];\n"
                 : "=r"(r0), "=r"(r1), "=r"(r2), "=r"(r3) : "r"(addr));
}
__device__ __forceinline__ void mma_bf16(float c[4], const uint32_t a[4], const uint32_t b[2]) {
    asm volatile(
        "mma.sync.aligned.m16n8k16.row.col.f32.bf16.bf16.f32 "
        "{%0,%1,%2,%3}, {%4,%5,%6,%7}, {%8,%9}, {%0,%1,%2,%3};\n"
        : "+f"(c[0]), "+f"(c[1]), "+f"(c[2]), "+f"(c[3])
        : "r"(a[0]), "r"(a[1]), "r"(a[2]), "r"(a[3]), "r"(b[0]), "r"(b[1]));
}

// ---------------- one window GEMM: out[32 rows, 64 cols @ wa] ----------------
// A: 32 rows (m0..) x K; W: rows [wa, wa+64) x K. K tiles of 32.
// For k0 >= winStart, A fragments come from the smem a1 window (layer-2 fresh cols).
// outSplit=1: relu+bias -> split bf16 to a1win smem + g_a1; 0: fp32 to a2win + g_a2.
__device__ __forceinline__ void gemm_phase(
    uint32_t smemBase, float* a2w, bf16* a1wHi, bf16* a1wLo,
    int m0, int wa, int kend, int winStart,
    const bf16* __restrict__ Ahi_g, const bf16* __restrict__ Alo_g,
    const bf16* __restrict__ Whi_g, const bf16* __restrict__ Wlo_g,
    const float* __restrict__ bias, int outSplit,
    bf16* __restrict__ gOutHi, bf16* __restrict__ gOutLo,
    float* __restrict__ gOutF) {

    const int tid = (int)threadIdx.x;
    const int lane = tid & 31;
    const int wid = tid >> 5;
    const int wm = wid & 1;       // 2 M sub-tiles of 16
    const int wn = wid >> 1;      // 4 N sub-tiles of 16
    const int g = lane >> 2;
    const int tg = lane & 3;
    const int lrow = lane & 15;
    const int lkof = (lane >> 4) << 3;

    float c[2][4] = {};
    const int nIter = kend >> 5;

    auto prefetch = [&](int buf, int k0) {
        uint32_t sb = smemBase + (uint32_t)(buf * STG_BYTES);
        if (k0 < winStart) {
            int half = tid >> 7;               // 0..1 (hi/lo)
            int row = (tid >> 2) & 31;
            int ch = tid & 3;
            const bf16* src = (half ? Alo_g : Ahi_g) + (size_t)(m0 + row) * Hh + k0 + ch * 8;
            cp16(sb + (uint32_t)((half ? 1280 : 0) + row * 40 + ch * 8) * 2u, src);
        }
#pragma unroll
        for (int i = 0; i < 2; i++) {
            int idx2 = tid + i * 256;          // 0..511
            int half = idx2 >> 8;
            int r = (idx2 & 255) >> 2;
            int ch = idx2 & 3;
            const bf16* src = (half ? Wlo_g : Whi_g) + (size_t)(wa + r) * Hh + k0 + ch * 8;
            cp16(sb + (uint32_t)(2560 + (half ? 2560 : 0) + r * 40 + ch * 8) * 2u, src);
        }
    };

    prefetch(0, 0);
    cp_commit();

    const uint32_t a1wHiU = smem_u32(a1wHi);
    const uint32_t a1wLoU = smem_u32(a1wLo);

    for (int it = 0; it < nIter; it++) {
        const int buf = it & 1;
        if (it + 1 < nIter) prefetch(buf ^ 1, (it + 1) * 32);
        cp_commit();
        cp_wait1();
        __syncthreads();

        const int k0 = it * 32;
        const uint32_t sb = smemBase + (uint32_t)(buf * STG_BYTES);
        const bool win = (k0 >= winStart);
        const int cw = win ? ((k0 - winStart) >> 5) : 0;

#pragma unroll
        for (int kst = 0; kst < 2; kst++) {
            const int ks = kst * 16;
            const uint32_t aoff = (uint32_t)((wm * 16 + lrow) * 40 + ks + lkof) * 2u;
            uint32_t ah[4], al[4];
            if (win) {
                ldsm4(ah[0], ah[1], ah[2], ah[3], a1wHiU + (uint32_t)(cw * 2560) + aoff);
                ldsm4(al[0], al[1], al[2], al[3], a1wLoU + (uint32_t)(cw * 2560) + aoff);
            } else {
                ldsm4(ah[0], ah[1], ah[2], ah[3], sb + aoff);
                ldsm4(al[0], al[1], al[2], al[3], sb + 2560u + aoff);
            }
            const uint32_t boff = (uint32_t)((wn * 16 + lrow) * 40 + ks + lkof) * 2u;
            uint32_t t0, t1, t2, t3;
            uint32_t bh[2][2], bl[2][2];
            ldsm4(t0, t1, t2, t3, sb + 5120u + boff);
            bh[0][0] = t0; bh[0][1] = t2; bh[1][0] = t1; bh[1][1] = t3;
            ldsm4(t0, t1, t2, t3, sb + 10240u + boff);
            bl[0][0] = t0; bl[0][1] = t2; bl[1][0] = t1; bl[1][1] = t3;

            mma_bf16(c[0], ah, bh[0]);
            mma_bf16(c[1], ah, bh[1]);
            mma_bf16(c[0], al, bh[0]);
            mma_bf16(c[1], al, bh[1]);
            mma_bf16(c[0], ah, bl[0]);
            mma_bf16(c[1], ah, bl[1]);
        }
        __syncthreads();
    }

    // ---- epilogue ----
    const int r0 = wm * 16 + g;
#pragma unroll
    for (int ni = 0; ni < 2; ni++) {
#pragma unroll
        for (int q = 0; q < 2; q++) {
            int cl = wn * 16 + ni * 8 + tg * 2 + q;   // 0..63 window-local col
            int col = wa + cl;
            float bv = bias[col];
            float y0 = fmaxf(c[ni][q] + bv, 0.f);       // row r0
            float y1 = fmaxf(c[ni][q + 2] + bv, 0.f);   // row r0+8
            if (outSplit) {
                int ck = cl >> 5, cc = cl & 31;
                bf16 h0 = __float2bfloat16_rn(y0);
                bf16 h1 = __float2bfloat16_rn(y1);
                bf16 l0 = __float2bfloat16_rn(y0 - __bfloat162float(h0));
                bf16 l1 = __float2bfloat16_rn(y1 - __bfloat162float(h1));
                a1wHi[ck * 1280 + r0 * 40 + cc] = h0;
                a1wHi[ck * 1280 + (r0 + 8) * 40 + cc] = h1;
                a1wLo[ck * 1280 + r0 * 40 + cc] = l0;
                a1wLo[ck * 1280 + (r0 + 8) * 40 + cc] = l1;
                gOutHi[(size_t)(m0 + r0) * Hh + col] = h0;
                gOutHi[(size_t)(m0 + r0 + 8) * Hh + col] = h1;
                gOutLo[(size_t)(m0 + r0) * Hh + col] = l0;
                gOutLo[(size_t)(m0 + r0 + 8) * Hh + col] = l1;
            } else {
                a2w[r0 * 65 + cl] = y0;
                a2w[(r0 + 8) * 65 + cl] = y1;
                gOutF[(size_t)(m0 + r0) * Hh + col] = y0;
                gOutF[(size_t)(m0 + r0 + 8) * Hh + col] = y1;
            }
        }
    }
}

// ---------------- finish: outputs + incremental pre0 update (row-local) -------
__device__ __forceinline__ void finish_phase(const float* __restrict__ z,
                                             const float* __restrict__ bout,
                                             float* __restrict__ x,
                                             const float* a2w,
                                             int m0, int idx, int h, int wa) {
    const int wid = (int)threadIdx.x >> 5;
    const int lane = (int)threadIdx.x & 31;
    const float* wmu = g_Wos + (size_t)idx * Hh;
    const float* wls = g_Wos + (size_t)(idx + Dd) * Hh;
    const float* w0c = g_W0sT + idx * Hh;

#pragma unroll
    for (int rr = 0; rr < 4; rr++) {
        int r = wid * 4 + rr;
        int row = m0 + r;
        float smu = 0.f, sls = 0.f;
        const float* arow = g_a2 + (size_t)row * Hh;
        for (int cc = lane; cc < wa; cc += 32) {
            float av = arow[cc];
            smu += av * wmu[cc];
            sls += av * wls[cc];
        }
        for (int cc = wa + lane; cc < h; cc += 32) {
            float av = a2w[r * 65 + (cc - wa)];
            smu += av * wmu[cc];
            sls += av * wls[cc];
        }
#pragma unroll
        for (int o = 16; o; o >>= 1) {
            smu += __shfl_xor_sync(0xffffffffu, smu, o);
            sls += __shfl_xor_sync(0xffffffffu, sls, o);
        }
        float mu = smu + bout[idx];
        float ls = sls + bout[idx + Dd];
        float xi = z[(size_t)row * Dd + idx] * expf(ls) + mu;
        if (lane == 0) x[(size_t)row * Dd + idx] = xi;

        float* prow = g_pre0 + (size_t)row * Hh;
        bf16* ph = g_p0hi + (size_t)row * Hh;
        bf16* pl = g_p0lo + (size_t)row * Hh;
        for (int s2 = h + lane; s2 < Hh; s2 += 32) {
            float v = prow[s2] + w0c[s2] * xi;
            prow[s2] = v;
            float y = fmaxf(v, 0.f);
            bf16 hi = __float2bfloat16_rn(y);
            ph[s2] = hi;
            pl[s2] = __float2bfloat16_rn(y - __bfloat162float(hi));
        }
    }
}

// ---------------- the whole 32-step loop, one launch, zero inter-CTA sync ------
__global__ __launch_bounds__(256, 1) void step_kernel(const float* __restrict__ z,
                                                      const float* __restrict__ bout,
                                                      float* __restrict__ x) {
    extern __shared__ char smraw[];
    const uint32_t smemBase = smem_u32(smraw);
    bf16* a1wHi = (bf16*)(smraw + A1W_HI);
    bf16* a1wLo = (bf16*)(smraw + A1W_LO);
    float* a2w = (float*)(smraw + A2W_OFF);
    const int m0 = (int)blockIdx.x * BMs;

    for (int idx = 0; idx < Dd; idx++) {
        const int h = idx ? (33 * idx + 1) : 0;
        int wa = 0;
        if (idx) {
            int hp = h - 33;
            wa = hp & ~31;
            if (wa > 960) wa = 960;
            int kend1 = (h + 31) & ~31;
            if (kend1 > Hh) kend1 = Hh;
            // layer 1: A = split(relu(pre0)); window cols [wa, wa+64)
            gemm_phase(smemBase, a2w, a1wHi, a1wLo, m0, wa, kend1, 1 << 30,
                       g_p0hi, g_p0lo, g_Wh_hi, g_Wh_lo, g_bhs, 1,
                       g_a1hi, g_a1lo, nullptr);
            __syncthreads();
            // layer 2: A = a1 (global prefix + fresh smem window)
            gemm_phase(smemBase, a2w, a1wHi, a1wLo, m0, wa, wa + 64, wa,
                       g_a1hi, g_a1lo, g_Wh_hi + Hh * Hh, g_Wh_lo + Hh * Hh,
                       g_bhs + Hh, 0, nullptr, nullptr, g_a2);
            __syncthreads();
        }
        finish_phase(z, bout, x, a2w, m0, idx, h, wa);
        __syncthreads();
    }
}

// ---------------- launch ----------------
extern "C" void kernel_launch(void* const* d_in, const int* in_sizes, int n_in,
                              void* d_out, int out_size) {
    const float* z    = (const float*)d_in[0];
    const float* W0   = (const float*)d_in[1];
    const float* b0   = (const float*)d_in[2];
    const float* Wh   = (const float*)d_in[3];
    const float* bh   = (const float*)d_in[4];
    const float* Wout = (const float*)d_in[5];
    const float* bout = (const float*)d_in[6];
    float* x = (float*)d_out;

    static int attrSet = 0;
    if (!attrSet) {
        cudaFuncSetAttribute(step_kernel, cudaFuncAttributeMaxDynamicSharedMemorySize,
                             SMEMB);
        attrSet = 1;
    }

    prep_kernel<<<1024, 256>>>(W0, b0, Wh, bh, Wout);
    step_kernel<<<NCTA, 256, SMEMB>>>(z, bout, x);
}

// round 9
// speedup vs baseline: 3.5085x; 1.5229x over previous
#include <cuda_runtime.h>
#include <cuda_bf16.h>
#include <math.h>
#include <stdint.h>

// Problem constants
#define Dd 32
#define Hh 1024
#define Ll 2
#define Bb 4096
#define BMs 32
#define NCTA 128
#define NT 512

typedef __nv_bfloat16 bf16;

// ---------------- device scratch (static, no allocation) ----------------
__device__ bf16  g_p0hi[Bb * Hh];       // split(relu(pre0)), materialized lazily
__device__ bf16  g_p0lo[Bb * Hh];
__device__ bf16  g_a1hi[Bb * Hh];
__device__ bf16  g_a1lo[Bb * Hh];
__device__ float g_a2[Bb * Hh];
__device__ bf16  g_Wh_hi[Ll * Hh * Hh];
__device__ bf16  g_Wh_lo[Ll * Hh * Hh];
__device__ float g_bhs[Ll * Hh];
__device__ float g_W0r[Hh * Dd];        // masked sorted W0, row-major [t][j]
__device__ float g_b0s[Hh];             // permuted b0
__device__ float g_Wos[2 * Dd * Hh];

// Degree-sorted permutation. Hidden degree of original unit i is i % 31.
__device__ __forceinline__ int permS(int s) {
    return (s < 34) ? 31 * s : ((s - 1) / 33) + 31 * ((s - 1) % 33);
}
__device__ __forceinline__ int degS(int s) {
    return (s < 34) ? 0 : (s - 1) / 33;
}

// ---------------- weight pre-transform ----------------
__global__ void prep_kernel(const float* __restrict__ W0,
                            const float* __restrict__ b0,
                            const float* __restrict__ Wh,
                            const float* __restrict__ bh,
                            const float* __restrict__ Wout) {
    int stride = gridDim.x * blockDim.x;
    int tid0 = blockIdx.x * blockDim.x + threadIdx.x;

    for (int i = tid0; i < Ll * Hh * Hh; i += stride) {
        int l = i >> 20;
        int rem = i & (Hh * Hh - 1);
        int s = rem >> 10;
        int t = rem & (Hh - 1);
        float v = 0.f;
        if (degS(s) >= degS(t)) v = Wh[l * Hh * Hh + permS(s) * Hh + permS(t)];
        bf16 hi = __float2bfloat16_rn(v);
        g_Wh_hi[i] = hi;
        g_Wh_lo[i] = __float2bfloat16_rn(v - __bfloat162float(hi));
    }
    for (int i = tid0; i < Ll * Hh; i += stride) {
        int l = i >> 10;
        int s = i & (Hh - 1);
        g_bhs[i] = bh[l * Hh + permS(s)];
    }
    for (int i = tid0; i < Hh * Dd; i += stride) {
        int t = i >> 5;           // sorted hidden unit
        int j = i & 31;           // input col
        g_W0r[i] = (degS(t) >= j) ? W0[permS(t) * Dd + j] : 0.f;
    }
    for (int i = tid0; i < Hh; i += stride) g_b0s[i] = b0[permS(i)];
    for (int i = tid0; i < 2 * Dd * Hh; i += stride) {
        int o = i >> 10;
        int t = i & (Hh - 1);
        g_Wos[i] = (((o & 31) - 1) >= degS(t)) ? Wout[o * Hh + permS(t)] : 0.f;
    }
}

// ---------------- smem layout (bytes) ----------------
// 3 cp.async stages @0: each {Ahi 2560 | Alo 2560 | Bhi 5120 | Blo 5120} = 15360
// p0 window  hi@46080 lo@51200 : 2 chunks x [32][40] bf16 (5120 B each)
// a1 window  hi@56320 lo@61440 : 2 chunks x [32][40] bf16
// a2 window  @66560 : [32][65] fp32 (8320 B)
// xs         @74880 : [32][33] fp32 (4224 B)
#define STGB 15360
#define P0W_HI 46080
#define P0W_LO 51200
#define A1W_HI 56320
#define A1W_LO 61440
#define A2W_OFF 66560
#define XS_OFF 74880
#define SMEMB 79104

__device__ __forceinline__ uint32_t smem_u32(const void* p) {
    return (uint32_t)__cvta_generic_to_shared(p);
}
__device__ __forceinline__ void cp16(uint32_t dst, const void* src) {
    asm volatile("cp.async.cg.shared.global [%0], [%1], 16;\n" :: "r"(dst), "l"(src));
}
__device__ __forceinline__ void cp_commit() { asm volatile("cp.async.commit_group;\n"); }
__device__ __forceinline__ void cp_wait2() { asm volatile("cp.async.wait_group 2;\n"); }
__device__ __forceinline__ void ldsm4(uint32_t& r0, uint32_t& r1, uint32_t& r2,
                                      uint32_t& r3, uint32_t addr) {
    asm volatile("ldmatrix.sync.aligned.m8n8.x4.shared.b16 {%0,%1,%2,%3}, [%4];\n"
                 : "=r"(r0), "=r"(r1), "=r"(r2), "=r"(r3) : "r"(addr));
}
__device__ __forceinline__ void mma_bf16(float c[4], const uint32_t a[4], const uint32_t b[2]) {
    asm volatile(
        "mma.sync.aligned.m16n8k16.row.col.f32.bf16.bf16.f32 "
        "{%0,%1,%2,%3}, {%4,%5,%6,%7}, {%8,%9}, {%0,%1,%2,%3};\n"
        : "+f"(c[0]), "+f"(c[1]), "+f"(c[2]), "+f"(c[3])
        : "r"(a[0]), "r"(a[1]), "r"(a[2]), "r"(a[3]), "r"(b[0]), "r"(b[1]));
}

// ---------------- window GEMM: out[32 rows, 64 cols @ wa] ----------------
// K tiles of 32 over [0, kend). For k0 >= winStart, A comes from the smem
// window (2 chunks of [32][40] hi/lo); else from global split A via cp.async.
// outSplit=1: relu+bias -> bf16 split to a1 window + g_a1.
// outSplit=0: relu+bias -> fp32 to a2 window + g_a2.
__device__ __forceinline__ void gemm_phase(
    uint32_t smemBase, uint32_t winHiU, uint32_t winLoU, int winStart,
    int m0, int wa, int kend,
    const bf16* __restrict__ Ahi_g, const bf16* __restrict__ Alo_g,
    const bf16* __restrict__ Whi_g, const bf16* __restrict__ Wlo_g,
    const float* __restrict__ bias, int outSplit,
    bf16* __restrict__ gOutHi, bf16* __restrict__ gOutLo,
    float* __restrict__ gOutF,
    bf16* a1wHi, bf16* a1wLo, float* a2w) {

    const int tid = (int)threadIdx.x;
    const int lane = tid & 31;
    const int wid = tid >> 5;
    const int wm = wid & 1;       // 2 x m16
    const int wn = wid >> 1;      // 8 x n8
    const int lrow = lane & 15;
    const int lkof = (lane >> 4) << 3;

    float c[4] = {0.f, 0.f, 0.f, 0.f};
    const int nIter = kend >> 5;

    auto prefetch = [&](int buf, int k0) {
        uint32_t sb = smemBase + (uint32_t)(buf * STGB);
        if (k0 < winStart && tid < 256) {
            int half = tid >> 7;                 // hi/lo
            int row = (tid >> 2) & 31;
            int ch = tid & 3;
            const bf16* src = (half ? Alo_g : Ahi_g) + (size_t)(m0 + row) * Hh + k0 + ch * 8;
            cp16(sb + (uint32_t)((half ? 1280 : 0) + row * 40 + ch * 8) * 2u, src);
        }
        {
            int half = tid >> 8;
            int r = (tid & 255) >> 2;            // 0..63
            int ch = tid & 3;
            const bf16* src = (half ? Wlo_g : Whi_g) + (size_t)(wa + r) * Hh + k0 + ch * 8;
            cp16(sb + (uint32_t)(2560 + (half ? 2560 : 0) + r * 40 + ch * 8) * 2u, src);
        }
    };

    prefetch(0, 0);
    cp_commit();
    prefetch(1, 32);
    cp_commit();

    // B ldsm address: 8 n-rows x 4 k-quadrants covers n8 x k32 per x4
    const uint32_t boff = (uint32_t)((wn * 8 + (lane & 7)) * 40 + ((lane >> 3) << 3)) * 2u;

    for (int it = 0; it < nIter; it++) {
        const int buf = it % 3;
        if (it + 2 < nIter) prefetch((it + 2) % 3, (it + 2) * 32);
        cp_commit();
        cp_wait2();
        __syncthreads();

        const int k0 = it * 32;
        const uint32_t sb = smemBase + (uint32_t)(buf * STGB);
        uint32_t aBaseHi, aBaseLo;
        if (k0 >= winStart) {
            uint32_t cw = (uint32_t)((k0 - winStart) >> 5) * 2560u;  // chunk bytes
            aBaseHi = winHiU + cw;
            aBaseLo = winLoU + cw;
        } else {
            aBaseHi = sb;
            aBaseLo = sb + 2560u;
        }

        uint32_t bh[4], bl[4];
        ldsm4(bh[0], bh[1], bh[2], bh[3], sb + 5120u + boff);
        ldsm4(bl[0], bl[1], bl[2], bl[3], sb + 10240u + boff);

#pragma unroll
        for (int kst = 0; kst < 2; kst++) {
            const uint32_t aoff = (uint32_t)((wm * 16 + lrow) * 40 + kst * 16 + lkof) * 2u;
            uint32_t ah[4], al[4];
            ldsm4(ah[0], ah[1], ah[2], ah[3], aBaseHi + aoff);
            ldsm4(al[0], al[1], al[2], al[3], aBaseLo + aoff);
            mma_bf16(c, ah, &bh[kst * 2]);
            mma_bf16(c, al, &bh[kst * 2]);
            mma_bf16(c, ah, &bl[kst * 2]);
        }
        __syncthreads();
    }

    // ---- epilogue: 4 outputs per warp ----
    const int r0 = wm * 16 + (lane >> 2);
    const int tg = lane & 3;
#pragma unroll
    for (int q = 0; q < 2; q++) {
        int cl = wn * 8 + tg * 2 + q;     // 0..63 window-local col
        int col = wa + cl;
        float bv = bias[col];
        float y0 = fmaxf(c[q] + bv, 0.f);         // row r0
        float y1 = fmaxf(c[q + 2] + bv, 0.f);     // row r0+8
        if (outSplit) {
            int ck = cl >> 5, cc = cl & 31;
            bf16 h0 = __float2bfloat16_rn(y0);
            bf16 h1 = __float2bfloat16_rn(y1);
            bf16 l0 = __float2bfloat16_rn(y0 - __bfloat162float(h0));
            bf16 l1 = __float2bfloat16_rn(y1 - __bfloat162float(h1));
            a1wHi[ck * 1280 + r0 * 40 + cc] = h0;
            a1wHi[ck * 1280 + (r0 + 8) * 40 + cc] = h1;
            a1wLo[ck * 1280 + r0 * 40 + cc] = l0;
            a1wLo[ck * 1280 + (r0 + 8) * 40 + cc] = l1;
            gOutHi[(size_t)(m0 + r0) * Hh + col] = h0;
            gOutHi[(size_t)(m0 + r0 + 8) * Hh + col] = h1;
            gOutLo[(size_t)(m0 + r0) * Hh + col] = l0;
            gOutLo[(size_t)(m0 + r0 + 8) * Hh + col] = l1;
        } else {
            a2w[r0 * 65 + cl] = y0;
            a2w[(r0 + 8) * 65 + cl] = y1;
            gOutF[(size_t)(m0 + r0) * Hh + col] = y0;
            gOutF[(size_t)(m0 + r0 + 8) * Hh + col] = y1;
        }
    }
}

// ---------------- lazy pre0 materialization: cols [msA, kend) ----------------
__device__ __forceinline__ void materialize(const float* xs, int m0, int msA,
                                            int kend, int idx,
                                            bf16* p0wHi, bf16* p0wLo) {
    const int tid = (int)threadIdx.x;
    const int n = (kend - msA) * 32;
    for (int i = tid; i < n; i += NT) {
        int r = i & 31;
        int t = msA + (i >> 5);
        const float* wr = g_W0r + t * Dd;
        float acc = g_b0s[t];
        for (int j = 0; j < idx; j++) acc = fmaf(wr[j], xs[r * 33 + j], acc);
        float y = fmaxf(acc, 0.f);
        bf16 hi = __float2bfloat16_rn(y);
        bf16 lo = __float2bfloat16_rn(y - __bfloat162float(hi));
        int cl = t - msA;
        p0wHi[(cl >> 5) * 1280 + r * 40 + (cl & 31)] = hi;
        p0wLo[(cl >> 5) * 1280 + r * 40 + (cl & 31)] = lo;
        g_p0hi[(size_t)(m0 + r) * Hh + t] = hi;
        g_p0lo[(size_t)(m0 + r) * Hh + t] = lo;
    }
}

// ---------------- finish: mu/ls + x update (row-local) ----------------
__device__ __forceinline__ void finish_phase(const float* __restrict__ z,
                                             const float* __restrict__ bout,
                                             float* __restrict__ x,
                                             const float* a2w, float* xs,
                                             int m0, int idx, int h, int wa) {
    const int wid = (int)threadIdx.x >> 5;
    const int lane = (int)threadIdx.x & 31;
    const float* wmu = g_Wos + (size_t)idx * Hh;
    const float* wls = g_Wos + (size_t)(idx + Dd) * Hh;

#pragma unroll
    for (int rr = 0; rr < 2; rr++) {
        int r = wid * 2 + rr;
        int row = m0 + r;
        float smu = 0.f, sls = 0.f;
        const float* arow = g_a2 + (size_t)row * Hh;
        for (int cc = lane; cc < wa; cc += 32) {
            float av = arow[cc];
            smu = fmaf(av, wmu[cc], smu);
            sls = fmaf(av, wls[cc], sls);
        }
        for (int cc = wa + lane; cc < h; cc += 32) {
            float av = a2w[r * 65 + (cc - wa)];
            smu = fmaf(av, wmu[cc], smu);
            sls = fmaf(av, wls[cc], sls);
        }
#pragma unroll
        for (int o = 16; o; o >>= 1) {
            smu += __shfl_xor_sync(0xffffffffu, smu, o);
            sls += __shfl_xor_sync(0xffffffffu, sls, o);
        }
        float mu = smu + bout[idx];
        float ls = sls + bout[idx + Dd];
        float xi = z[(size_t)row * Dd + idx] * expf(ls) + mu;
        if (lane == 0) {
            x[(size_t)row * Dd + idx] = xi;
            xs[r * 33 + idx] = xi;
        }
    }
}

// ---------------- persistent-per-CTA 32-step loop (no inter-CTA sync) -------
__global__ __launch_bounds__(NT, 1) void step_kernel(const float* __restrict__ z,
                                                     const float* __restrict__ bout,
                                                     float* __restrict__ x) {
    extern __shared__ char smraw[];
    const uint32_t smemBase = smem_u32(smraw);
    bf16* p0wHi = (bf16*)(smraw + P0W_HI);
    bf16* p0wLo = (bf16*)(smraw + P0W_LO);
    bf16* a1wHi = (bf16*)(smraw + A1W_HI);
    bf16* a1wLo = (bf16*)(smraw + A1W_LO);
    float* a2w = (float*)(smraw + A2W_OFF);
    float* xs = (float*)(smraw + XS_OFF);
    const int m0 = (int)blockIdx.x * BMs;

    for (int idx = 0; idx < Dd; idx++) {
        const int h = idx ? (33 * idx + 1) : 0;
        int wa = 0;
        if (idx) {
            const int ms = (idx > 1) ? (33 * (idx - 1) + 1) : 0;
            const int msA = ms & ~31;
            int kend1 = (h + 31) & ~31;
            materialize(xs, m0, msA, kend1, idx, p0wHi, p0wLo);
            __syncthreads();
            wa = (h - 33) & ~31;
            if (wa > 960) wa = 960;
            // layer 1: A = split(relu(pre0)); prefix global, fresh cols from p0 window
            gemm_phase(smemBase, smem_u32(p0wHi), smem_u32(p0wLo), msA,
                       m0, wa, kend1,
                       g_p0hi, g_p0lo, g_Wh_hi, g_Wh_lo, g_bhs,
                       1, g_a1hi, g_a1lo, nullptr, a1wHi, a1wLo, a2w);
            __syncthreads();
            // layer 2: A = a1; prefix global, fresh window in smem
            gemm_phase(smemBase, smem_u32(a1wHi), smem_u32(a1wLo), wa,
                       m0, wa, wa + 64,
                       g_a1hi, g_a1lo, g_Wh_hi + Hh * Hh, g_Wh_lo + Hh * Hh,
                       g_bhs + Hh, 0, nullptr, nullptr, g_a2, a1wHi, a1wLo, a2w);
            __syncthreads();
        }
        finish_phase(z, bout, x, a2w, xs, m0, idx, h, wa);
        __syncthreads();
    }
}

// ---------------- launch ----------------
extern "C" void kernel_launch(void* const* d_in, const int* in_sizes, int n_in,
                              void* d_out, int out_size) {
    const float* z    = (const float*)d_in[0];
    const float* W0   = (const float*)d_in[1];
    const float* b0   = (const float*)d_in[2];
    const float* Wh   = (const float*)d_in[3];
    const float* bh   = (const float*)d_in[4];
    const float* Wout = (const float*)d_in[5];
    const float* bout = (const float*)d_in[6];
    float* x = (float*)d_out;

    static int attrSet = 0;
    if (!attrSet) {
        cudaFuncSetAttribute(step_kernel, cudaFuncAttributeMaxDynamicSharedMemorySize,
                             SMEMB);
        attrSet = 1;
    }

    prep_kernel<<<1024, 256>>>(W0, b0, Wh, bh, Wout);
    step_kernel<<<NCTA, NT, SMEMB>>>(z, bout, x);
}

// round 10
// speedup vs baseline: 3.6435x; 1.0385x over previous
#include <cuda_runtime.h>
#include <cuda_bf16.h>
#include <math.h>
#include <stdint.h>

// Problem constants
#define Dd 32
#define Hh 1024
#define Ll 2
#define Bb 4096
#define BMs 32
#define NCTA 128
#define NT 512

typedef __nv_bfloat16 bf16;

// ---------------- device scratch (static, no allocation) ----------------
__device__ bf16  g_p0hi[Bb * Hh];       // split(relu(pre0)), materialized lazily
__device__ bf16  g_p0lo[Bb * Hh];
__device__ bf16  g_a1hi[Bb * Hh];
__device__ bf16  g_a1lo[Bb * Hh];
__device__ float g_a2[Bb * Hh];
__device__ bf16  g_Wh_hi[Ll * Hh * Hh];
__device__ bf16  g_Wh_lo[Ll * Hh * Hh];
__device__ float g_bhs[Ll * Hh];
__device__ float g_W0r[Hh * Dd];        // masked sorted W0, row-major [t][j]
__device__ float g_b0s[Hh];             // permuted b0
__device__ float g_Wos[2 * Dd * Hh];

// Degree-sorted permutation. Hidden degree of original unit i is i % 31.
__device__ __forceinline__ int permS(int s) {
    return (s < 34) ? 31 * s : ((s - 1) / 33) + 31 * ((s - 1) % 33);
}
__device__ __forceinline__ int degS(int s) {
    return (s < 34) ? 0 : (s - 1) / 33;
}

// ---------------- weight pre-transform ----------------
__global__ void prep_kernel(const float* __restrict__ W0,
                            const float* __restrict__ b0,
                            const float* __restrict__ Wh,
                            const float* __restrict__ bh,
                            const float* __restrict__ Wout) {
    int stride = gridDim.x * blockDim.x;
    int tid0 = blockIdx.x * blockDim.x + threadIdx.x;

    for (int i = tid0; i < Ll * Hh * Hh; i += stride) {
        int l = i >> 20;
        int rem = i & (Hh * Hh - 1);
        int s = rem >> 10;
        int t = rem & (Hh - 1);
        float v = 0.f;
        if (degS(s) >= degS(t)) v = Wh[l * Hh * Hh + permS(s) * Hh + permS(t)];
        bf16 hi = __float2bfloat16_rn(v);
        g_Wh_hi[i] = hi;
        g_Wh_lo[i] = __float2bfloat16_rn(v - __bfloat162float(hi));
    }
    for (int i = tid0; i < Ll * Hh; i += stride) {
        int l = i >> 10;
        int s = i & (Hh - 1);
        g_bhs[i] = bh[l * Hh + permS(s)];
    }
    for (int i = tid0; i < Hh * Dd; i += stride) {
        int t = i >> 5;           // sorted hidden unit
        int j = i & 31;           // input col
        g_W0r[i] = (degS(t) >= j) ? W0[permS(t) * Dd + j] : 0.f;
    }
    for (int i = tid0; i < Hh; i += stride) g_b0s[i] = b0[permS(i)];
    for (int i = tid0; i < 2 * Dd * Hh; i += stride) {
        int o = i >> 10;
        int t = i & (Hh - 1);
        g_Wos[i] = (((o & 31) - 1) >= degS(t)) ? Wout[o * Hh + permS(t)] : 0.f;
    }
}

// ---------------- smem layout (bytes) ----------------
// 5 cp.async stages @0: each {Ahi 2560 | Alo 2560 | Bhi 5120 | Blo 5120} = 15360
// p0 window  hi@76800 lo@81920 : 2 chunks x [32][40] bf16 (5120 B each)
// a1 window  hi@87040 lo@92160
// a2 window  @97280 : [32][65] fp32 (8320 B)
// xs         @105600 : [32][33] fp32 (4224 B)
#define STGB 15360
#define P0W_HI 76800
#define P0W_LO 81920
#define A1W_HI 87040
#define A1W_LO 92160
#define A2W_OFF 97280
#define XS_OFF 105600
#define SMEMB 109824

__device__ __forceinline__ uint32_t smem_u32(const void* p) {
    return (uint32_t)__cvta_generic_to_shared(p);
}
__device__ __forceinline__ void cp16(uint32_t dst, const void* src) {
    asm volatile("cp.async.cg.shared.global [%0], [%1], 16;\n" :: "r"(dst), "l"(src));
}
__device__ __forceinline__ void cp_commit() { asm volatile("cp.async.commit_group;\n"); }
__device__ __forceinline__ void cp_wait3() { asm volatile("cp.async.wait_group 3;\n"); }
__device__ __forceinline__ void ldsm4(uint32_t& r0, uint32_t& r1, uint32_t& r2,
                                      uint32_t& r3, uint32_t addr) {
    asm volatile("ldmatrix.sync.aligned.m8n8.x4.shared.b16 {%0,%1,%2,%3}, [%4];\n"
                 : "=r"(r0), "=r"(r1), "=r"(r2), "=r"(r3) : "r"(addr));
}
__device__ __forceinline__ void mma_bf16(float c[4], const uint32_t a[4], const uint32_t b[2]) {
    asm volatile(
        "mma.sync.aligned.m16n8k16.row.col.f32.bf16.bf16.f32 "
        "{%0,%1,%2,%3}, {%4,%5,%6,%7}, {%8,%9}, {%0,%1,%2,%3};\n"
        : "+f"(c[0]), "+f"(c[1]), "+f"(c[2]), "+f"(c[3])
        : "r"(a[0]), "r"(a[1]), "r"(a[2]), "r"(a[3]), "r"(b[0]), "r"(b[1]));
}

// ---------------- window GEMM: out[32 rows, 64 cols @ wa] ----------------
// 5-stage cp.async ring, fetch-ahead 3, ONE __syncthreads per K-iteration.
// Safety: prefetch at iter `it` writes stage (it+3)%5 == (it-2)%5; the barrier
// at iter it-1 guarantees every warp finished compute(it-2).
__device__ __forceinline__ void gemm_phase(
    uint32_t smemBase, uint32_t winHiU, uint32_t winLoU, int winStart,
    int m0, int wa, int kend,
    const bf16* __restrict__ Ahi_g, const bf16* __restrict__ Alo_g,
    const bf16* __restrict__ Whi_g, const bf16* __restrict__ Wlo_g,
    const float* __restrict__ bias, int outSplit,
    bf16* __restrict__ gOutHi, bf16* __restrict__ gOutLo,
    float* __restrict__ gOutF,
    bf16* a1wHi, bf16* a1wLo, float* a2w) {

    const int tid = (int)threadIdx.x;
    const int lane = tid & 31;
    const int wid = tid >> 5;
    const int wm = wid & 1;       // 2 x m16
    const int wn = wid >> 1;      // 8 x n8
    const int lrow = lane & 15;
    const int lkof = (lane >> 4) << 3;

    float c[4] = {0.f, 0.f, 0.f, 0.f};
    const int nIter = kend >> 5;

    auto prefetch = [&](int buf, int k0) {
        uint32_t sb = smemBase + (uint32_t)(buf * STGB);
        if (k0 < winStart && tid < 256) {
            int half = tid >> 7;                 // hi/lo
            int row = (tid >> 2) & 31;
            int ch = tid & 3;
            const bf16* src = (half ? Alo_g : Ahi_g) + (size_t)(m0 + row) * Hh + k0 + ch * 8;
            cp16(sb + (uint32_t)((half ? 1280 : 0) + row * 40 + ch * 8) * 2u, src);
        }
        {
            int half = tid >> 8;
            int r = (tid & 255) >> 2;            // 0..63
            int ch = tid & 3;
            const bf16* src = (half ? Wlo_g : Whi_g) + (size_t)(wa + r) * Hh + k0 + ch * 8;
            cp16(sb + (uint32_t)(2560 + (half ? 2560 : 0) + r * 40 + ch * 8) * 2u, src);
        }
    };

    // preamble: 3 stages in flight
    prefetch(0, 0);  cp_commit();
    prefetch(1, 32); cp_commit();
    prefetch(2, 64); cp_commit();

    // B ldsm address: 8 n-rows x 4 k-quadrants covers n8 x k32 per x4
    const uint32_t boff = (uint32_t)((wn * 8 + (lane & 7)) * 40 + ((lane >> 3) << 3)) * 2u;

    for (int it = 0; it < nIter; it++) {
        const int buf = it % 5;
        if (it + 3 < nIter) prefetch((it + 3) % 5, (it + 3) * 32);
        cp_commit();
        cp_wait3();
        __syncthreads();

        const int k0 = it * 32;
        const uint32_t sb = smemBase + (uint32_t)(buf * STGB);
        uint32_t aBaseHi, aBaseLo;
        if (k0 >= winStart) {
            uint32_t cw = (uint32_t)((k0 - winStart) >> 5) * 2560u;  // chunk bytes
            aBaseHi = winHiU + cw;
            aBaseLo = winLoU + cw;
        } else {
            aBaseHi = sb;
            aBaseLo = sb + 2560u;
        }

        uint32_t bh[4], bl[4];
        ldsm4(bh[0], bh[1], bh[2], bh[3], sb + 5120u + boff);
        ldsm4(bl[0], bl[1], bl[2], bl[3], sb + 10240u + boff);

#pragma unroll
        for (int kst = 0; kst < 2; kst++) {
            const uint32_t aoff = (uint32_t)((wm * 16 + lrow) * 40 + kst * 16 + lkof) * 2u;
            uint32_t ah[4], al[4];
            ldsm4(ah[0], ah[1], ah[2], ah[3], aBaseHi + aoff);
            ldsm4(al[0], al[1], al[2], al[3], aBaseLo + aoff);
            mma_bf16(c, ah, &bh[kst * 2]);
            mma_bf16(c, al, &bh[kst * 2]);
            mma_bf16(c, ah, &bl[kst * 2]);
        }
        // no trailing sync: 5-stage ring + per-iter barrier keeps stages safe
    }

    // ---- epilogue: 4 outputs per warp ----
    const int r0 = wm * 16 + (lane >> 2);
    const int tg = lane & 3;
#pragma unroll
    for (int q = 0; q < 2; q++) {
        int cl = wn * 8 + tg * 2 + q;     // 0..63 window-local col
        int col = wa + cl;
        float bv = bias[col];
        float y0 = fmaxf(c[q] + bv, 0.f);         // row r0
        float y1 = fmaxf(c[q + 2] + bv, 0.f);     // row r0+8
        if (outSplit) {
            int ck = cl >> 5, cc = cl & 31;
            bf16 h0 = __float2bfloat16_rn(y0);
            bf16 h1 = __float2bfloat16_rn(y1);
            bf16 l0 = __float2bfloat16_rn(y0 - __bfloat162float(h0));
            bf16 l1 = __float2bfloat16_rn(y1 - __bfloat162float(h1));
            a1wHi[ck * 1280 + r0 * 40 + cc] = h0;
            a1wHi[ck * 1280 + (r0 + 8) * 40 + cc] = h1;
            a1wLo[ck * 1280 + r0 * 40 + cc] = l0;
            a1wLo[ck * 1280 + (r0 + 8) * 40 + cc] = l1;
            gOutHi[(size_t)(m0 + r0) * Hh + col] = h0;
            gOutHi[(size_t)(m0 + r0 + 8) * Hh + col] = h1;
            gOutLo[(size_t)(m0 + r0) * Hh + col] = l0;
            gOutLo[(size_t)(m0 + r0 + 8) * Hh + col] = l1;
        } else {
            a2w[r0 * 65 + cl] = y0;
            a2w[(r0 + 8) * 65 + cl] = y1;
            gOutF[(size_t)(m0 + r0) * Hh + col] = y0;
            gOutF[(size_t)(m0 + r0 + 8) * Hh + col] = y1;
        }
    }
}

// ---------------- lazy pre0 materialization: cols [msA, kend) ----------------
__device__ __forceinline__ void materialize(const float* xs, int m0, int msA,
                                            int kend, int idx,
                                            bf16* p0wHi, bf16* p0wLo) {
    const int tid = (int)threadIdx.x;
    const int n = (kend - msA) * 32;
    for (int i = tid; i < n; i += NT) {
        int r = i & 31;
        int t = msA + (i >> 5);
        const float* wr = g_W0r + t * Dd;
        float acc = g_b0s[t];
        for (int j = 0; j < idx; j++) acc = fmaf(wr[j], xs[r * 33 + j], acc);
        float y = fmaxf(acc, 0.f);
        bf16 hi = __float2bfloat16_rn(y);
        bf16 lo = __float2bfloat16_rn(y - __bfloat162float(hi));
        int cl = t - msA;
        p0wHi[(cl >> 5) * 1280 + r * 40 + (cl & 31)] = hi;
        p0wLo[(cl >> 5) * 1280 + r * 40 + (cl & 31)] = lo;
        g_p0hi[(size_t)(m0 + r) * Hh + t] = hi;
        g_p0lo[(size_t)(m0 + r) * Hh + t] = lo;
    }
}

// ---------------- finish: mu/ls + x update (row-local) ----------------
__device__ __forceinline__ void finish_phase(const float* __restrict__ z,
                                             const float* __restrict__ bout,
                                             float* __restrict__ x,
                                             const float* a2w, float* xs,
                                             int m0, int idx, int h, int wa) {
    const int wid = (int)threadIdx.x >> 5;
    const int lane = (int)threadIdx.x & 31;
    const float* wmu = g_Wos + (size_t)idx * Hh;
    const float* wls = g_Wos + (size_t)(idx + Dd) * Hh;

#pragma unroll
    for (int rr = 0; rr < 2; rr++) {
        int r = wid * 2 + rr;
        int row = m0 + r;
        float smu = 0.f, sls = 0.f;
        const float* arow = g_a2 + (size_t)row * Hh;
        for (int cc = lane; cc < wa; cc += 32) {
            float av = arow[cc];
            smu = fmaf(av, wmu[cc], smu);
            sls = fmaf(av, wls[cc], sls);
        }
        for (int cc = wa + lane; cc < h; cc += 32) {
            float av = a2w[r * 65 + (cc - wa)];
            smu = fmaf(av, wmu[cc], smu);
            sls = fmaf(av, wls[cc], sls);
        }
#pragma unroll
        for (int o = 16; o; o >>= 1) {
            smu += __shfl_xor_sync(0xffffffffu, smu, o);
            sls += __shfl_xor_sync(0xffffffffu, sls, o);
        }
        float mu = smu + bout[idx];
        float ls = sls + bout[idx + Dd];
        float xi = z[(size_t)row * Dd + idx] * expf(ls) + mu;
        if (lane == 0) {
            x[(size_t)row * Dd + idx] = xi;
            xs[r * 33 + idx] = xi;
        }
    }
}

// ---------------- persistent-per-CTA 32-step loop (no inter-CTA sync) -------
__global__ __launch_bounds__(NT, 1) void step_kernel(const float* __restrict__ z,
                                                     const float* __restrict__ bout,
                                                     float* __restrict__ x) {
    extern __shared__ char smraw[];
    const uint32_t smemBase = smem_u32(smraw);
    bf16* p0wHi = (bf16*)(smraw + P0W_HI);
    bf16* p0wLo = (bf16*)(smraw + P0W_LO);
    bf16* a1wHi = (bf16*)(smraw + A1W_HI);
    bf16* a1wLo = (bf16*)(smraw + A1W_LO);
    float* a2w = (float*)(smraw + A2W_OFF);
    float* xs = (float*)(smraw + XS_OFF);
    const int m0 = (int)blockIdx.x * BMs;

    for (int idx = 0; idx < Dd; idx++) {
        const int h = idx ? (33 * idx + 1) : 0;
        int wa = 0;
        if (idx) {
            const int ms = (idx > 1) ? (33 * (idx - 1) + 1) : 0;
            const int msA = ms & ~31;
            int kend1 = (h + 31) & ~31;
            materialize(xs, m0, msA, kend1, idx, p0wHi, p0wLo);
            __syncthreads();
            wa = (h - 33) & ~31;
            if (wa > 960) wa = 960;
            // layer 1: A = split(relu(pre0)); prefix global, fresh cols from p0 window
            gemm_phase(smemBase, smem_u32(p0wHi), smem_u32(p0wLo), msA,
                       m0, wa, kend1,
                       g_p0hi, g_p0lo, g_Wh_hi, g_Wh_lo, g_bhs,
                       1, g_a1hi, g_a1lo, nullptr, a1wHi, a1wLo, a2w);
            __syncthreads();
            // layer 2: A = a1; prefix global, fresh window in smem
            gemm_phase(smemBase, smem_u32(a1wHi), smem_u32(a1wLo), wa,
                       m0, wa, wa + 64,
                       g_a1hi, g_a1lo, g_Wh_hi + Hh * Hh, g_Wh_lo + Hh * Hh,
                       g_bhs + Hh, 0, nullptr, nullptr, g_a2, a1wHi, a1wLo, a2w);
            __syncthreads();
        }
        finish_phase(z, bout, x, a2w, xs, m0, idx, h, wa);
        __syncthreads();
    }
}

// ---------------- launch ----------------
extern "C" void kernel_launch(void* const* d_in, const int* in_sizes, int n_in,
                              void* d_out, int out_size) {
    const float* z    = (const float*)d_in[0];
    const float* W0   = (const float*)d_in[1];
    const float* b0   = (const float*)d_in[2];
    const float* Wh   = (const float*)d_in[3];
    const float* bh   = (const float*)d_in[4];
    const float* Wout = (const float*)d_in[5];
    const float* bout = (const float*)d_in[6];
    float* x = (float*)d_out;

    static int attrSet = 0;
    if (!attrSet) {
        cudaFuncSetAttribute(step_kernel, cudaFuncAttributeMaxDynamicSharedMemorySize,
                             SMEMB);
        attrSet = 1;
    }

    prep_kernel<<<1024, 256>>>(W0, b0, Wh, bh, Wout);
    step_kernel<<<NCTA, NT, SMEMB>>>(z, bout, x);
}

// round 11
// speedup vs baseline: 4.8328x; 1.3264x over previous
#include <cuda_runtime.h>
#include <cuda_fp16.h>
#include <math.h>
#include <stdint.h>

// Problem constants
#define Dd 32
#define Hh 1024
#define Ll 2
#define Bb 4096
#define BMs 32
#define NCTA 128
#define NT 512

typedef __half fp16;

// ---------------- device scratch (static, no allocation) ----------------
__device__ fp16  g_p0[Bb * Hh];         // fp16(relu(pre0)), materialized lazily
__device__ fp16  g_a1[Bb * Hh];         // layer-1 activations fp16
__device__ float g_a2[Bb * Hh];         // layer-2 activations fp32
__device__ fp16  g_Wh_hi[Ll * Hh * Hh]; // masked+sorted hidden weights fp16 hi
__device__ fp16  g_Wh_lo[Ll * Hh * Hh]; // fp16 lo residual
__device__ float g_bhs[Ll * Hh];
__device__ float g_W0r[Hh * Dd];        // masked sorted W0, row-major [t][j]
__device__ float g_b0s[Hh];             // permuted b0
__device__ float g_Wos[2 * Dd * Hh];

// Degree-sorted permutation. Hidden degree of original unit i is i % 31.
__device__ __forceinline__ int permS(int s) {
    return (s < 34) ? 31 * s : ((s - 1) / 33) + 31 * ((s - 1) % 33);
}
__device__ __forceinline__ int degS(int s) {
    return (s < 34) ? 0 : (s - 1) / 33;
}

// ---------------- weight pre-transform ----------------
__global__ void prep_kernel(const float* __restrict__ W0,
                            const float* __restrict__ b0,
                            const float* __restrict__ Wh,
                            const float* __restrict__ bh,
                            const float* __restrict__ Wout) {
    int stride = gridDim.x * blockDim.x;
    int tid0 = blockIdx.x * blockDim.x + threadIdx.x;

    for (int i = tid0; i < Ll * Hh * Hh; i += stride) {
        int l = i >> 20;
        int rem = i & (Hh * Hh - 1);
        int s = rem >> 10;
        int t = rem & (Hh - 1);
        float v = 0.f;
        if (degS(s) >= degS(t)) v = Wh[l * Hh * Hh + permS(s) * Hh + permS(t)];
        fp16 hi = __float2half_rn(v);
        g_Wh_hi[i] = hi;
        g_Wh_lo[i] = __float2half_rn(v - __half2float(hi));
    }
    for (int i = tid0; i < Ll * Hh; i += stride) {
        int l = i >> 10;
        int s = i & (Hh - 1);
        g_bhs[i] = bh[l * Hh + permS(s)];
    }
    for (int i = tid0; i < Hh * Dd; i += stride) {
        int t = i >> 5;
        int j = i & 31;
        g_W0r[i] = (degS(t) >= j) ? W0[permS(t) * Dd + j] : 0.f;
    }
    for (int i = tid0; i < Hh; i += stride) g_b0s[i] = b0[permS(i)];
    for (int i = tid0; i < 2 * Dd * Hh; i += stride) {
        int o = i >> 10;
        int t = i & (Hh - 1);
        g_Wos[i] = (((o & 31) - 1) >= degS(t)) ? Wout[o * Hh + permS(t)] : 0.f;
    }
}

// ---------------- smem layout (bytes) ----------------
// 5 cp.async stages @0: each {A 2560 | Bhi 5120 | Blo 5120} = 12800
// p0 window @64000 : 2 chunks x [32][40] fp16 (2560 B each)
// a1 window @69120
// a2 window @74240 : [32][65] fp32 (8320 B)
// xs        @82560 : [32][33] fp32 (4224 B)
#define STGB 12800
#define P0W_OFF 64000
#define A1W_OFF 69120
#define A2W_OFF 74240
#define XS_OFF 82560
#define SMEMB 86784

__device__ __forceinline__ uint32_t smem_u32(const void* p) {
    return (uint32_t)__cvta_generic_to_shared(p);
}
__device__ __forceinline__ void cp16(uint32_t dst, const void* src) {
    asm volatile("cp.async.cg.shared.global [%0], [%1], 16;\n" :: "r"(dst), "l"(src));
}
__device__ __forceinline__ void cp_commit() { asm volatile("cp.async.commit_group;\n"); }
__device__ __forceinline__ void cp_wait3() { asm volatile("cp.async.wait_group 3;\n"); }
__device__ __forceinline__ void ldsm4(uint32_t& r0, uint32_t& r1, uint32_t& r2,
                                      uint32_t& r3, uint32_t addr) {
    asm volatile("ldmatrix.sync.aligned.m8n8.x4.shared.b16 {%0,%1,%2,%3}, [%4];\n"
                 : "=r"(r0), "=r"(r1), "=r"(r2), "=r"(r3) : "r"(addr));
}
__device__ __forceinline__ void mma_fp16(float c[4], const uint32_t a[4], const uint32_t b[2]) {
    asm volatile(
        "mma.sync.aligned.m16n8k16.row.col.f32.f16.f16.f32 "
        "{%0,%1,%2,%3}, {%4,%5,%6,%7}, {%8,%9}, {%0,%1,%2,%3};\n"
        : "+f"(c[0]), "+f"(c[1]), "+f"(c[2]), "+f"(c[3])
        : "r"(a[0]), "r"(a[1]), "r"(a[2]), "r"(a[3]), "r"(b[0]), "r"(b[1]));
}

// ---------------- window GEMM: out[32 rows, 64 cols @ wa] ----------------
// fp16 2-pass: A single fp16 (2^-11 rounding), W split hi/lo fp16.
// 5-stage cp.async ring, fetch-ahead 3, one __syncthreads per K-iteration.
__device__ __forceinline__ void gemm_phase(
    uint32_t smemBase, uint32_t winU, int winStart,
    int m0, int wa, int kend,
    const fp16* __restrict__ A_g,
    const fp16* __restrict__ Whi_g, const fp16* __restrict__ Wlo_g,
    const float* __restrict__ bias, int outSplit,
    fp16* __restrict__ gOutH, float* __restrict__ gOutF,
    fp16* a1w, float* a2w) {

    const int tid = (int)threadIdx.x;
    const int lane = tid & 31;
    const int wid = tid >> 5;
    const int wm = wid & 1;       // 2 x m16
    const int wn = wid >> 1;      // 8 x n8
    const int lrow = lane & 15;
    const int lkof = (lane >> 4) << 3;

    float cH[4] = {0.f, 0.f, 0.f, 0.f};
    float cL[4] = {0.f, 0.f, 0.f, 0.f};
    const int nIter = kend >> 5;

    auto prefetch = [&](int buf, int k0) {
        uint32_t sb = smemBase + (uint32_t)(buf * STGB);
        if (k0 < winStart && tid < 128) {
            int row = tid >> 2;                  // 0..31
            int ch = tid & 3;
            const fp16* src = A_g + (size_t)(m0 + row) * Hh + k0 + ch * 8;
            cp16(sb + (uint32_t)(row * 40 + ch * 8) * 2u, src);
        }
        {
            int half = tid >> 8;                 // hi/lo
            int r = (tid & 255) >> 2;            // 0..63
            int ch = tid & 3;
            const fp16* src = (half ? Wlo_g : Whi_g) + (size_t)(wa + r) * Hh + k0 + ch * 8;
            cp16(sb + 2560u + (half ? 5120u : 0u) + (uint32_t)(r * 40 + ch * 8) * 2u, src);
        }
    };

    prefetch(0, 0);  cp_commit();
    prefetch(1, 32); cp_commit();
    prefetch(2, 64); cp_commit();

    // B ldsm: 8 n-rows x 4 k-quadrants covers n8 x k32 per x4
    const uint32_t boff = (uint32_t)((wn * 8 + (lane & 7)) * 40 + ((lane >> 3) << 3)) * 2u;

    for (int it = 0; it < nIter; it++) {
        const int buf = it % 5;
        if (it + 3 < nIter) prefetch((it + 3) % 5, (it + 3) * 32);
        cp_commit();
        cp_wait3();
        __syncthreads();

        const int k0 = it * 32;
        const uint32_t sb = smemBase + (uint32_t)(buf * STGB);
        uint32_t aBase;
        if (k0 >= winStart) {
            aBase = winU + (uint32_t)((k0 - winStart) >> 5) * 2560u;
        } else {
            aBase = sb;
        }

        uint32_t bh[4], bl[4];
        ldsm4(bh[0], bh[1], bh[2], bh[3], sb + 2560u + boff);
        ldsm4(bl[0], bl[1], bl[2], bl[3], sb + 7680u + boff);

#pragma unroll
        for (int kst = 0; kst < 2; kst++) {
            const uint32_t aoff = (uint32_t)((wm * 16 + lrow) * 40 + kst * 16 + lkof) * 2u;
            uint32_t a[4];
            ldsm4(a[0], a[1], a[2], a[3], aBase + aoff);
            mma_fp16(cH, a, &bh[kst * 2]);     // two independent chains for ILP
            mma_fp16(cL, a, &bl[kst * 2]);
        }
    }

    // ---- epilogue: 4 outputs per warp ----
    const int r0 = wm * 16 + (lane >> 2);
    const int tg = lane & 3;
#pragma unroll
    for (int q = 0; q < 2; q++) {
        int cl = wn * 8 + tg * 2 + q;     // 0..63 window-local col
        int col = wa + cl;
        float bv = bias[col];
        float y0 = fmaxf(cH[q] + cL[q] + bv, 0.f);           // row r0
        float y1 = fmaxf(cH[q + 2] + cL[q + 2] + bv, 0.f);   // row r0+8
        if (outSplit) {
            int ck = cl >> 5, cc = cl & 31;
            fp16 h0 = __float2half_rn(y0);
            fp16 h1 = __float2half_rn(y1);
            a1w[ck * 1280 + r0 * 40 + cc] = h0;
            a1w[ck * 1280 + (r0 + 8) * 40 + cc] = h1;
            gOutH[(size_t)(m0 + r0) * Hh + col] = h0;
            gOutH[(size_t)(m0 + r0 + 8) * Hh + col] = h1;
        } else {
            a2w[r0 * 65 + cl] = y0;
            a2w[(r0 + 8) * 65 + cl] = y1;
            gOutF[(size_t)(m0 + r0) * Hh + col] = y0;
            gOutF[(size_t)(m0 + r0 + 8) * Hh + col] = y1;
        }
    }
}

// ---------------- lazy pre0 materialization: cols [msA, kend) ----------------
__device__ __forceinline__ void materialize(const float* xs, int m0, int msA,
                                            int kend, int idx, fp16* p0w) {
    const int tid = (int)threadIdx.x;
    const int n = (kend - msA) * 32;
    for (int i = tid; i < n; i += NT) {
        int r = i & 31;
        int t = msA + (i >> 5);
        const float* wr = g_W0r + t * Dd;
        float acc = g_b0s[t];
        for (int j = 0; j < idx; j++) acc = fmaf(wr[j], xs[r * 33 + j], acc);
        float y = fmaxf(acc, 0.f);
        fp16 hv = __float2half_rn(y);
        int cl = t - msA;
        p0w[(cl >> 5) * 1280 + r * 40 + (cl & 31)] = hv;
        g_p0[(size_t)(m0 + r) * Hh + t] = hv;
    }
}

// ---------------- finish: mu/ls + x update (row-local) ----------------
__device__ __forceinline__ void finish_phase(const float* __restrict__ z,
                                             const float* __restrict__ bout,
                                             float* __restrict__ x,
                                             const float* a2w, float* xs,
                                             int m0, int idx, int h, int wa) {
    const int wid = (int)threadIdx.x >> 5;
    const int lane = (int)threadIdx.x & 31;
    const float* wmu = g_Wos + (size_t)idx * Hh;
    const float* wls = g_Wos + (size_t)(idx + Dd) * Hh;

#pragma unroll
    for (int rr = 0; rr < 2; rr++) {
        int r = wid * 2 + rr;
        int row = m0 + r;
        float smu = 0.f, sls = 0.f;
        const float* arow = g_a2 + (size_t)row * Hh;
        for (int cc = lane; cc < wa; cc += 32) {
            float av = arow[cc];
            smu = fmaf(av, wmu[cc], smu);
            sls = fmaf(av, wls[cc], sls);
        }
        for (int cc = wa + lane; cc < h; cc += 32) {
            float av = a2w[r * 65 + (cc - wa)];
            smu = fmaf(av, wmu[cc], smu);
            sls = fmaf(av, wls[cc], sls);
        }
#pragma unroll
        for (int o = 16; o; o >>= 1) {
            smu += __shfl_xor_sync(0xffffffffu, smu, o);
            sls += __shfl_xor_sync(0xffffffffu, sls, o);
        }
        float mu = smu + bout[idx];
        float ls = sls + bout[idx + Dd];
        float xi = z[(size_t)row * Dd + idx] * expf(ls) + mu;
        if (lane == 0) {
            x[(size_t)row * Dd + idx] = xi;
            xs[r * 33 + idx] = xi;
        }
    }
}

// ---------------- persistent-per-CTA 32-step loop (no inter-CTA sync) -------
__global__ __launch_bounds__(NT, 1) void step_kernel(const float* __restrict__ z,
                                                     const float* __restrict__ bout,
                                                     float* __restrict__ x) {
    extern __shared__ char smraw[];
    const uint32_t smemBase = smem_u32(smraw);
    fp16* p0w = (fp16*)(smraw + P0W_OFF);
    fp16* a1w = (fp16*)(smraw + A1W_OFF);
    float* a2w = (float*)(smraw + A2W_OFF);
    float* xs = (float*)(smraw + XS_OFF);
    const int m0 = (int)blockIdx.x * BMs;

    for (int idx = 0; idx < Dd; idx++) {
        const int h = idx ? (33 * idx + 1) : 0;
        int wa = 0;
        if (idx) {
            const int ms = (idx > 1) ? (33 * (idx - 1) + 1) : 0;
            const int msA = ms & ~31;
            int kend1 = (h + 31) & ~31;
            materialize(xs, m0, msA, kend1, idx, p0w);
            __syncthreads();
            wa = (h - 33) & ~31;
            if (wa > 960) wa = 960;
            // layer 1: A = fp16(relu(pre0)); prefix global, fresh cols from p0 window
            gemm_phase(smemBase, smem_u32(p0w), msA, m0, wa, kend1,
                       g_p0, g_Wh_hi, g_Wh_lo, g_bhs,
                       1, g_a1, nullptr, a1w, a2w);
            __syncthreads();
            // layer 2: A = a1; prefix global, fresh window in smem
            gemm_phase(smemBase, smem_u32(a1w), wa, m0, wa, wa + 64,
                       g_a1, g_Wh_hi + Hh * Hh, g_Wh_lo + Hh * Hh,
                       g_bhs + Hh, 0, nullptr, g_a2, a1w, a2w);
            __syncthreads();
        }
        finish_phase(z, bout, x, a2w, xs, m0, idx, h, wa);
        __syncthreads();
    }
}

// ---------------- launch ----------------
extern "C" void kernel_launch(void* const* d_in, const int* in_sizes, int n_in,
                              void* d_out, int out_size) {
    const float* z    = (const float*)d_in[0];
    const float* W0   = (const float*)d_in[1];
    const float* b0   = (const float*)d_in[2];
    const float* Wh   = (const float*)d_in[3];
    const float* bh   = (const float*)d_in[4];
    const float* Wout = (const float*)d_in[5];
    const float* bout = (const float*)d_in[6];
    float* x = (float*)d_out;

    static int attrSet = 0;
    if (!attrSet) {
        cudaFuncSetAttribute(step_kernel, cudaFuncAttributeMaxDynamicSharedMemorySize,
                             SMEMB);
        attrSet = 1;
    }

    prep_kernel<<<1024, 256>>>(W0, b0, Wh, bh, Wout);
    step_kernel<<<NCTA, NT, SMEMB>>>(z, bout, x);
}

// round 12
// speedup vs baseline: 5.5112x; 1.1404x over previous
#include <cuda_runtime.h>
#include <cuda_fp16.h>
#include <math.h>
#include <stdint.h>

// Problem constants
#define Dd 32
#define Hh 1024
#define Ll 2
#define Bb 4096
#define BMs 32
#define NCTA 128
#define NT 512

typedef __half fp16;

// ---------------- device scratch (static, no allocation) ----------------
// Packed activation layout: [cta][kchunk 32][row 32][32 k] with 16B-swizzle
// q' = (kk>>3) ^ ((row>>1)&3); element = chunk*1024 + row*32 + q'*8 + (kk&7)
__device__ fp16  g_p0p[NCTA * 32 * 1024];   // packed fp16(relu(pre0))
__device__ fp16  g_a1p[NCTA * 32 * 1024];   // packed layer-1 activations
__device__ float g_a2[Bb * Hh];             // layer-2 activations fp32 (plain)
// Packed weights: per (layer l, window jw 0..30, kchunk kc 0..31): 8KB tile =
// [hi: 64 rows x 32 k][lo: same], swizzled like activations.
__device__ fp16  g_Whp[2 * 31 * 32 * 4096];
__device__ float g_bhs[Ll * Hh];
__device__ float g_W0r[Hh * Dd];            // masked sorted W0, row-major [t][j]
__device__ float g_b0s[Hh];                 // permuted b0
__device__ float g_Wos[2 * Dd * Hh];

// Degree-sorted permutation. Hidden degree of original unit i is i % 31.
__device__ __forceinline__ int permS(int s) {
    return (s < 34) ? 31 * s : ((s - 1) / 33) + 31 * ((s - 1) % 33);
}
__device__ __forceinline__ int degS(int s) {
    return (s < 34) ? 0 : (s - 1) / 33;
}

// ---------------- weight pre-transform ----------------
__global__ void prep_kernel(const float* __restrict__ W0,
                            const float* __restrict__ b0,
                            const float* __restrict__ Wh,
                            const float* __restrict__ bh,
                            const float* __restrict__ Wout) {
    int stride = gridDim.x * blockDim.x;
    int tid0 = blockIdx.x * blockDim.x + threadIdx.x;

    // packed masked sorted hidden weights, split hi/lo fp16
    for (int i = tid0; i < 2 * 31 * 32 * 64 * 32; i += stride) {
        int l = i / 2031616;
        int r1 = i % 2031616;
        int jw = r1 >> 16;            // /65536
        int r2 = r1 & 65535;
        int kc = r2 >> 11;
        int r3 = r2 & 2047;
        int row = r3 >> 5;
        int kk = r3 & 31;
        int s = jw * 32 + row;
        int t = kc * 32 + kk;
        float v = 0.f;
        if (degS(s) >= degS(t)) v = Wh[l * Hh * Hh + permS(s) * Hh + permS(t)];
        fp16 hi = __float2half_rn(v);
        fp16 lo = __float2half_rn(v - __half2float(hi));
        int base = ((l * 31 + jw) * 32 + kc) * 4096;
        int off = row * 32 + (((kk >> 3) ^ ((row >> 1) & 3)) << 3) + (kk & 7);
        g_Whp[base + off] = hi;
        g_Whp[base + 2048 + off] = lo;
    }
    for (int i = tid0; i < Ll * Hh; i += stride) {
        int l = i >> 10;
        int s = i & (Hh - 1);
        g_bhs[i] = bh[l * Hh + permS(s)];
    }
    for (int i = tid0; i < Hh * Dd; i += stride) {
        int t = i >> 5;
        int j = i & 31;
        g_W0r[i] = (degS(t) >= j) ? W0[permS(t) * Dd + j] : 0.f;
    }
    for (int i = tid0; i < Hh; i += stride) g_b0s[i] = b0[permS(i)];
    for (int i = tid0; i < 2 * Dd * Hh; i += stride) {
        int o = i >> 10;
        int t = i & (Hh - 1);
        g_Wos[i] = (((o & 31) - 1) >= degS(t)) ? Wout[o * Hh + permS(t)] : 0.f;
    }
}

// ---------------- smem layout (bytes) ----------------
// 5 bulk stages @0: each {A 2048 | Bhi 4096 | Blo 4096} = 10240
// p0 window @51200, a1 window @55296 : 2 chunks x 2048 B each (packed layout)
// a2 window @59392 : [32][65] fp32 (8320 B)
// xs        @67712 : [32][33] fp32 (4224 B)
// mbars     @71936 : 5 x 8 B
#define STGB 10240
#define P0W_OFF 51200
#define A1W_OFF 55296
#define A2W_OFF 59392
#define XS_OFF 67712
#define MBAR_OFF 71936
#define SMEMB 72192

__device__ __forceinline__ uint32_t smem_u32(const void* p) {
    return (uint32_t)__cvta_generic_to_shared(p);
}
__device__ __forceinline__ void cpbulk(uint32_t dst, const void* src,
                                       uint32_t bytes, uint32_t mbar) {
    asm volatile(
        "cp.async.bulk.shared::cta.global.mbarrier::complete_tx::bytes "
        "[%0], [%1], %2, [%3];\n"
        :: "r"(dst), "l"(src), "r"(bytes), "r"(mbar) : "memory");
}
__device__ __forceinline__ void mbar_init(uint32_t a, uint32_t cnt) {
    asm volatile("mbarrier.init.shared.b64 [%0], %1;" :: "r"(a), "r"(cnt) : "memory");
}
__device__ __forceinline__ void mbar_expect(uint32_t a, uint32_t bytes) {
    asm volatile("mbarrier.arrive.expect_tx.shared.b64 _, [%0], %1;"
                 :: "r"(a), "r"(bytes) : "memory");
}
__device__ __forceinline__ void mbar_wait(uint32_t mbar, uint32_t parity) {
    asm volatile(
        "{\n\t"
        ".reg .pred P;\n\t"
        "LW%=:\n\t"
        "mbarrier.try_wait.parity.acquire.cta.shared::cta.b64 P, [%0], %1, 0x989680;\n\t"
        "@P bra LD%=;\n\t"
        "bra LW%=;\n\t"
        "LD%=:\n\t"
        "}"
        :: "r"(mbar), "r"(parity) : "memory");
}
__device__ __forceinline__ void ldsm4(uint32_t& r0, uint32_t& r1, uint32_t& r2,
                                      uint32_t& r3, uint32_t addr) {
    asm volatile("ldmatrix.sync.aligned.m8n8.x4.shared.b16 {%0,%1,%2,%3}, [%4];\n"
                 : "=r"(r0), "=r"(r1), "=r"(r2), "=r"(r3) : "r"(addr));
}
__device__ __forceinline__ void mma_fp16(float c[4], const uint32_t a[4], const uint32_t b[2]) {
    asm volatile(
        "mma.sync.aligned.m16n8k16.row.col.f32.f16.f16.f32 "
        "{%0,%1,%2,%3}, {%4,%5,%6,%7}, {%8,%9}, {%0,%1,%2,%3};\n"
        : "+f"(c[0]), "+f"(c[1]), "+f"(c[2]), "+f"(c[3])
        : "r"(a[0]), "r"(a[1]), "r"(a[2]), "r"(a[3]), "r"(b[0]), "r"(b[1]));
}

// ---------------- window GEMM: out[32 rows, 64 cols @ wa] ----------------
// A: packed per-CTA chunks (bulk-copied) or smem window for k0 >= winStart.
// B: packed 8KB tiles (hi+lo), ONE bulk per stage. 5-stage mbarrier ring.
__device__ __forceinline__ void gemm_phase(
    uint32_t smemBase, uint32_t mbarBase, int& u,
    uint32_t winU, int winStart,
    int m0, int wa, int kend,
    const fp16* __restrict__ A_gp,      // packed A base for this CTA
    const fp16* __restrict__ B_gp,      // packed W base for (layer, window)
    const float* __restrict__ bias, int outSplit,
    float* __restrict__ gOutF, fp16* __restrict__ gA1p,
    fp16* a1w, float* a2w, int cta) {

    const int tid = (int)threadIdx.x;
    const int lane = tid & 31;
    const int wid = tid >> 5;
    const int wm = wid & 1;       // 2 x m16
    const int wn = wid >> 1;      // 8 x n8
    const int lrow = lane & 15;

    float cH[4] = {0.f, 0.f, 0.f, 0.f};
    float cL[4] = {0.f, 0.f, 0.f, 0.f};
    const int nIter = kend >> 5;
    const int u0 = u;

    auto issueStage = [&](int j) {
        int k0 = j * 32;
        int stage = (u0 + j) % 5;
        uint32_t mbar = mbarBase + stage * 8;
        uint32_t dstA = smemBase + (uint32_t)stage * STGB;
        uint32_t bytes = 8192u + ((k0 < winStart) ? 2048u : 0u);
        mbar_expect(mbar, bytes);
        if (k0 < winStart)
            cpbulk(dstA, A_gp + (size_t)(k0 >> 5) * 1024, 2048u, mbar);
        cpbulk(dstA + 2048u, B_gp + (size_t)(k0 >> 5) * 4096, 8192u, mbar);
    };

    if (tid == 0) {
        for (int j = 0; j < 3 && j < nIter; j++) issueStage(j);
    }

    // ldsm lane addressing (packed/swizzled layout)
    // A: row = wm*16+lrow, 16B quarter q = kst*2 + (lane>>4)
    // B: row = wn*8+(lane&7), quarter q = lane>>3
    const int aRow = wm * 16 + lrow;
    const int aSw = (aRow >> 1) & 3;
    const int bRow = wn * 8 + (lane & 7);
    const uint32_t bOff = (uint32_t)(bRow * 64 + (((lane >> 3) ^ ((bRow >> 1) & 3)) << 4));

    for (int it = 0; it < nIter; it++) {
        __syncthreads();
        if (tid == 0 && it + 3 < nIter) issueStage(it + 3);
        const int stage = (u0 + it) % 5;
        mbar_wait(mbarBase + stage * 8, (uint32_t)(((u0 + it) / 5) & 1));

        const int k0 = it * 32;
        const uint32_t sb = smemBase + (uint32_t)stage * STGB;
        uint32_t aBase;
        if (k0 >= winStart) {
            aBase = winU + (uint32_t)((k0 - winStart) >> 5) * 2048u;
        } else {
            aBase = sb;
        }

        uint32_t bh[4], bl[4];
        ldsm4(bh[0], bh[1], bh[2], bh[3], sb + 2048u + bOff);
        ldsm4(bl[0], bl[1], bl[2], bl[3], sb + 6144u + bOff);

#pragma unroll
        for (int kst = 0; kst < 2; kst++) {
            const int q = kst * 2 + (lane >> 4);
            const uint32_t aoff = (uint32_t)(aRow * 64 + ((q ^ aSw) << 4));
            uint32_t a[4];
            ldsm4(a[0], a[1], a[2], a[3], aBase + aoff);
            mma_fp16(cH, a, &bh[kst * 2]);
            mma_fp16(cL, a, &bl[kst * 2]);
        }
    }
    u = u0 + nIter;

    // ---- epilogue: 4 outputs per warp ----
    const int r0 = wm * 16 + (lane >> 2);
    const int tg = lane & 3;
#pragma unroll
    for (int q = 0; q < 2; q++) {
        int cl = wn * 8 + tg * 2 + q;     // 0..63 window-local col
        int col = wa + cl;
        float bv = bias[col];
        float y0 = fmaxf(cH[q] + cL[q] + bv, 0.f);           // row r0
        float y1 = fmaxf(cH[q + 2] + cL[q + 2] + bv, 0.f);   // row r0+8
        if (outSplit) {
            fp16 h0 = __float2half_rn(y0);
            fp16 h1 = __float2half_rn(y1);
            // packed writes: q' same for r0 and r0+8
            int kk = col & 31;
            int qp = (kk >> 3) ^ ((r0 >> 1) & 3);
            int eg = ((cta * 32 + (col >> 5)) * 32) * 32;    // base elems
            int e0 = eg + r0 * 32 + qp * 8 + (kk & 7);
            gA1p[e0] = h0;
            gA1p[e0 + 8 * 32] = h1;                          // row + 8
            int ew = ((cl >> 5) * 32 + r0) * 32 + qp * 8 + (kk & 7);
            a1w[ew] = h0;
            a1w[ew + 8 * 32] = h1;
        } else {
            a2w[r0 * 65 + cl] = y0;
            a2w[(r0 + 8) * 65 + cl] = y1;
            gOutF[(size_t)(m0 + r0) * Hh + col] = y0;
            gOutF[(size_t)(m0 + r0 + 8) * Hh + col] = y1;
        }
    }
}

// ---------------- lazy pre0 materialization: cols [msA, msA+64) ----------------
__device__ __forceinline__ void materialize(const float* xs, int cta, int msA,
                                            int idx, fp16* p0w) {
    const int tid = (int)threadIdx.x;
    for (int i = tid; i < 2048; i += NT) {
        int r = i & 31;
        int t = msA + (i >> 5);
        const float* wr = g_W0r + t * Dd;
        float acc = g_b0s[t];
        for (int j = 0; j < idx; j++) acc = fmaf(wr[j], xs[r * 33 + j], acc);
        float y = fmaxf(acc, 0.f);
        fp16 hv = __float2half_rn(y);
        int kk = t & 31;
        int qp = (kk >> 3) ^ ((r >> 1) & 3);
        g_p0p[((cta * 32 + (t >> 5)) * 32 + r) * 32 + qp * 8 + (kk & 7)] = hv;
        int cl = t - msA;
        p0w[((cl >> 5) * 32 + r) * 32 + qp * 8 + (kk & 7)] = hv;
    }
}

// ---------------- finish: mu/ls + x update (row-local) ----------------
__device__ __forceinline__ void finish_phase(const float* __restrict__ z,
                                             const float* __restrict__ bout,
                                             float* __restrict__ x,
                                             const float* a2w, float* xs,
                                             int m0, int idx, int h, int wa) {
    const int wid = (int)threadIdx.x >> 5;
    const int lane = (int)threadIdx.x & 31;
    const float* wmu = g_Wos + (size_t)idx * Hh;
    const float* wls = g_Wos + (size_t)(idx + Dd) * Hh;

#pragma unroll
    for (int rr = 0; rr < 2; rr++) {
        int r = wid * 2 + rr;
        int row = m0 + r;
        float smu = 0.f, sls = 0.f;
        const float* arow = g_a2 + (size_t)row * Hh;
        for (int cc = lane; cc < wa; cc += 32) {
            float av = arow[cc];
            smu = fmaf(av, wmu[cc], smu);
            sls = fmaf(av, wls[cc], sls);
        }
        for (int cc = wa + lane; cc < h; cc += 32) {
            float av = a2w[r * 65 + (cc - wa)];
            smu = fmaf(av, wmu[cc], smu);
            sls = fmaf(av, wls[cc], sls);
        }
#pragma unroll
        for (int o = 16; o; o >>= 1) {
            smu += __shfl_xor_sync(0xffffffffu, smu, o);
            sls += __shfl_xor_sync(0xffffffffu, sls, o);
        }
        float mu = smu + bout[idx];
        float ls = sls + bout[idx + Dd];
        float xi = z[(size_t)row * Dd + idx] * expf(ls) + mu;
        if (lane == 0) {
            x[(size_t)row * Dd + idx] = xi;
            xs[r * 33 + idx] = xi;
        }
    }
}

// ---------------- persistent-per-CTA 32-step loop (no inter-CTA sync) -------
__global__ __launch_bounds__(NT, 1) void step_kernel(const float* __restrict__ z,
                                                     const float* __restrict__ bout,
                                                     float* __restrict__ x) {
    extern __shared__ char smraw[];
    const uint32_t smemBase = smem_u32(smraw);
    const uint32_t mbarBase = smemBase + MBAR_OFF;
    fp16* p0w = (fp16*)(smraw + P0W_OFF);
    fp16* a1w = (fp16*)(smraw + A1W_OFF);
    float* a2w = (float*)(smraw + A2W_OFF);
    float* xs = (float*)(smraw + XS_OFF);
    const int cta = (int)blockIdx.x;
    const int m0 = cta * BMs;

    if (threadIdx.x == 0) {
        for (int s = 0; s < 5; s++) mbar_init(mbarBase + s * 8, 1);
    }
    __syncthreads();

    int u = 0;   // persistent stage-use counter (stage = u%5, parity = (u/5)&1)

    for (int idx = 0; idx < Dd; idx++) {
        const int h = idx ? (33 * idx + 1) : 0;
        int wa = 0;
        if (idx) {
            const int ms = (idx > 1) ? (33 * (idx - 1) + 1) : 0;
            const int msA = ms & ~31;
            const int kend1 = msA + 64;        // == (h+31)&~31
            materialize(xs, cta, msA, idx, p0w);
            __syncthreads();
            wa = (h - 33) & ~31;
            if (wa > 960) wa = 960;
            const int jw = wa >> 5;
            // layer 1: A = packed p0 (prefix bulk, fresh cols from p0 window)
            gemm_phase(smemBase, mbarBase, u, smem_u32(p0w), msA,
                       m0, wa, kend1,
                       g_p0p + (size_t)cta * 32768,
                       g_Whp + (size_t)jw * 32 * 4096,
                       g_bhs, 1, nullptr, g_a1p, a1w, a2w, cta);
            __syncthreads();
            // layer 2: A = packed a1 (prefix bulk, fresh window in smem)
            gemm_phase(smemBase, mbarBase, u, smem_u32(a1w), wa,
                       m0, wa, wa + 64,
                       g_a1p + (size_t)cta * 32768,
                       g_Whp + (size_t)(31 + jw) * 32 * 4096,
                       g_bhs + Hh, 0, g_a2, nullptr, a1w, a2w, cta);
            __syncthreads();
        }
        finish_phase(z, bout, x, a2w, xs, m0, idx, h, wa);
        __syncthreads();
    }
}

// ---------------- launch ----------------
extern "C" void kernel_launch(void* const* d_in, const int* in_sizes, int n_in,
                              void* d_out, int out_size) {
    const float* z    = (const float*)d_in[0];
    const float* W0   = (const float*)d_in[1];
    const float* b0   = (const float*)d_in[2];
    const float* Wh   = (const float*)d_in[3];
    const float* bh   = (const float*)d_in[4];
    const float* Wout = (const float*)d_in[5];
    const float* bout = (const float*)d_in[6];
    float* x = (float*)d_out;

    static int attrSet = 0;
    if (!attrSet) {
        cudaFuncSetAttribute(step_kernel, cudaFuncAttributeMaxDynamicSharedMemorySize,
                             SMEMB);
        attrSet = 1;
    }

    prep_kernel<<<1024, 256>>>(W0, b0, Wh, bh, Wout);
    step_kernel<<<NCTA, NT, SMEMB>>>(z, bout, x);
}

// round 13
// speedup vs baseline: 5.9720x; 1.0836x over previous
#include <cuda_runtime.h>
#include <cuda_fp16.h>
#include <math.h>
#include <stdint.h>

// Problem constants
#define Dd 32
#define Hh 1024
#define Ll 2
#define Bb 4096
#define BMs 32
#define NCTA 128
#define NT 512

typedef __half fp16;

// ---------------- device scratch (static, no allocation) ----------------
// Packed activation layout: [cta][kchunk 32][row 32][32 k] with 16B-swizzle
// q' = (kk>>3) ^ ((row>>1)&3); element = chunk*1024 + row*32 + q'*8 + (kk&7)
__device__ fp16  g_p0p[NCTA * 32 * 1024];   // packed fp16(relu(pre0))
__device__ fp16  g_a1p[NCTA * 32 * 1024];   // packed layer-1 activations
__device__ float g_a2[Bb * Hh];             // layer-2 activations fp32 (plain)
// Packed weights: per (layer l, window jw 0..30, kchunk kc 0..31): 8KB tile =
// [hi: 64 rows x 32 k][lo: same], swizzled like activations. kc-contiguous.
__device__ fp16  g_Whp[2 * 31 * 32 * 4096];
__device__ float g_bhs[Ll * Hh];
__device__ float g_W0r[Hh * Dd];            // masked sorted W0, row-major [t][j]
__device__ float g_b0s[Hh];                 // permuted b0
__device__ float g_Wos[2 * Dd * Hh];

// Degree-sorted permutation. Hidden degree of original unit i is i % 31.
__device__ __forceinline__ int permS(int s) {
    return (s < 34) ? 31 * s : ((s - 1) / 33) + 31 * ((s - 1) % 33);
}
__device__ __forceinline__ int degS(int s) {
    return (s < 34) ? 0 : (s - 1) / 33;
}

// ---------------- weight pre-transform ----------------
__global__ void prep_kernel(const float* __restrict__ W0,
                            const float* __restrict__ b0,
                            const float* __restrict__ Wh,
                            const float* __restrict__ bh,
                            const float* __restrict__ Wout) {
    int stride = gridDim.x * blockDim.x;
    int tid0 = blockIdx.x * blockDim.x + threadIdx.x;

    for (int i = tid0; i < 2 * 31 * 32 * 64 * 32; i += stride) {
        int l = i / 2031616;
        int r1 = i % 2031616;
        int jw = r1 >> 16;
        int r2 = r1 & 65535;
        int kc = r2 >> 11;
        int r3 = r2 & 2047;
        int row = r3 >> 5;
        int kk = r3 & 31;
        int s = jw * 32 + row;
        int t = kc * 32 + kk;
        float v = 0.f;
        if (degS(s) >= degS(t)) v = Wh[l * Hh * Hh + permS(s) * Hh + permS(t)];
        fp16 hi = __float2half_rn(v);
        fp16 lo = __float2half_rn(v - __half2float(hi));
        int base = ((l * 31 + jw) * 32 + kc) * 4096;
        int off = row * 32 + (((kk >> 3) ^ ((row >> 1) & 3)) << 3) + (kk & 7);
        g_Whp[base + off] = hi;
        g_Whp[base + 2048 + off] = lo;
    }
    for (int i = tid0; i < Ll * Hh; i += stride) {
        int l = i >> 10;
        int s = i & (Hh - 1);
        g_bhs[i] = bh[l * Hh + permS(s)];
    }
    for (int i = tid0; i < Hh * Dd; i += stride) {
        int t = i >> 5;
        int j = i & 31;
        g_W0r[i] = (degS(t) >= j) ? W0[permS(t) * Dd + j] : 0.f;
    }
    for (int i = tid0; i < Hh; i += stride) g_b0s[i] = b0[permS(i)];
    for (int i = tid0; i < 2 * Dd * Hh; i += stride) {
        int o = i >> 10;
        int t = i & (Hh - 1);
        g_Wos[i] = (((o & 31) - 1) >= degS(t)) ? Wout[o * Hh + permS(t)] : 0.f;
    }
}

// ---------------- smem layout (bytes) ----------------
// 4 bulk stages @0, each 64-k: {A 4096 | W(2 tiles: hi/lo interleaved) 16384} = 20480
// p0 window @81920, a1 window @86016 : 2 chunks x 2048 B each (packed layout)
// a2 window @90112 : [32][65] fp32 (8320 B)
// xs        @98432 : [32][33] fp32 (4224 B)
// mbars     @102656: 4 x 8 B
#define STGB 20480
#define P0W_OFF 81920
#define A1W_OFF 86016
#define A2W_OFF 90112
#define XS_OFF 98432
#define MBAR_OFF 102656
#define SMEMB 102912

__device__ __forceinline__ uint32_t smem_u32(const void* p) {
    return (uint32_t)__cvta_generic_to_shared(p);
}
__device__ __forceinline__ void cpbulk(uint32_t dst, const void* src,
                                       uint32_t bytes, uint32_t mbar) {
    asm volatile(
        "cp.async.bulk.shared::cta.global.mbarrier::complete_tx::bytes "
        "[%0], [%1], %2, [%3];\n"
        :: "r"(dst), "l"(src), "r"(bytes), "r"(mbar) : "memory");
}
__device__ __forceinline__ void mbar_init(uint32_t a, uint32_t cnt) {
    asm volatile("mbarrier.init.shared.b64 [%0], %1;" :: "r"(a), "r"(cnt) : "memory");
}
__device__ __forceinline__ void mbar_expect(uint32_t a, uint32_t bytes) {
    asm volatile("mbarrier.arrive.expect_tx.shared.b64 _, [%0], %1;"
                 :: "r"(a), "r"(bytes) : "memory");
}
__device__ __forceinline__ void mbar_wait(uint32_t mbar, uint32_t parity) {
    asm volatile(
        "{\n\t"
        ".reg .pred P;\n\t"
        "LW%=:\n\t"
        "mbarrier.try_wait.parity.acquire.cta.shared::cta.b64 P, [%0], %1, 0x989680;\n\t"
        "@P bra LD%=;\n\t"
        "bra LW%=;\n\t"
        "LD%=:\n\t"
        "}"
        :: "r"(mbar), "r"(parity) : "memory");
}
__device__ __forceinline__ void ldsm4(uint32_t& r0, uint32_t& r1, uint32_t& r2,
                                      uint32_t& r3, uint32_t addr) {
    asm volatile("ldmatrix.sync.aligned.m8n8.x4.shared.b16 {%0,%1,%2,%3}, [%4];\n"
                 : "=r"(r0), "=r"(r1), "=r"(r2), "=r"(r3) : "r"(addr));
}
__device__ __forceinline__ void mma_fp16(float c[4], const uint32_t a[4], const uint32_t b[2]) {
    asm volatile(
        "mma.sync.aligned.m16n8k16.row.col.f32.f16.f16.f32 "
        "{%0,%1,%2,%3}, {%4,%5,%6,%7}, {%8,%9}, {%0,%1,%2,%3};\n"
        : "+f"(c[0]), "+f"(c[1]), "+f"(c[2]), "+f"(c[3])
        : "r"(a[0]), "r"(a[1]), "r"(a[2]), "r"(a[3]), "r"(b[0]), "r"(b[1]));
}

// ---------------- window GEMM: out[32 rows, 64 cols @ wa] ----------------
// 64-k stages (2 chunks each): A packed chunks (bulk) or smem window for
// kc >= winStart; W packed 8KB tiles (hi+lo), ONE bulk per stage.
// 4-stage mbarrier ring, fetch-ahead 3, barrier-before-issue.
__device__ __forceinline__ void gemm_phase(
    uint32_t smemBase, uint32_t mbarBase, int& u,
    uint32_t winU, int winStart,
    int m0, int wa, int kend,
    const fp16* __restrict__ A_gp,      // packed A base for this CTA
    const fp16* __restrict__ B_gp,      // packed W base for (layer, window)
    const float* __restrict__ bias, int outSplit,
    float* __restrict__ gOutF, fp16* __restrict__ gA1p,
    fp16* a1w, float* a2w, int cta) {

    const int tid = (int)threadIdx.x;
    const int lane = tid & 31;
    const int wid = tid >> 5;
    const int wm = wid & 1;       // 2 x m16
    const int wn = wid >> 1;      // 8 x n8
    const int lrow = lane & 15;

    float cH[4] = {0.f, 0.f, 0.f, 0.f};
    float cL[4] = {0.f, 0.f, 0.f, 0.f};
    const int nIter = (kend + 63) >> 6;
    const int u0 = u;

    auto issueStage = [&](int j) {
        int k0 = j * 64;
        int stage = (u0 + j) & 3;
        uint32_t mbar = mbarBase + stage * 8;
        uint32_t dstA = smemBase + (uint32_t)stage * STGB;
        int kA = (winStart - k0) >> 5;           // #A chunks to copy (prefix)
        if (kA < 0) kA = 0; if (kA > 2) kA = 2;
        int rem = (kend - k0) >> 5;
        if (rem > 2) rem = 2;
        if (kA > rem) kA = rem;
        uint32_t bytes = (uint32_t)kA * 2048u + (uint32_t)rem * 8192u;
        mbar_expect(mbar, bytes);
        if (kA)
            cpbulk(dstA, A_gp + (size_t)(k0 >> 5) * 1024, (uint32_t)kA * 2048u, mbar);
        cpbulk(dstA + 4096u, B_gp + (size_t)(k0 >> 5) * 4096, (uint32_t)rem * 8192u, mbar);
    };

    if (tid == 0) {
        for (int j = 0; j < 3 && j < nIter; j++) issueStage(j);
    }

    // ldsm lane addressing (packed/swizzled layout)
    const int aRow = wm * 16 + lrow;
    const int aSw = (aRow >> 1) & 3;
    const int bRow = wn * 8 + (lane & 7);
    const uint32_t bOff = (uint32_t)(bRow * 64 + (((lane >> 3) ^ ((bRow >> 1) & 3)) << 4));

    for (int it = 0; it < nIter; it++) {
        __syncthreads();
        if (tid == 0 && it + 3 < nIter) issueStage(it + 3);
        const int stage = (u0 + it) & 3;
        mbar_wait(mbarBase + stage * 8, (uint32_t)(((u0 + it) >> 2) & 1));

        const uint32_t sb = smemBase + (uint32_t)stage * STGB;
        const int k0 = it * 64;

#pragma unroll
        for (int sub = 0; sub < 2; sub++) {
            const int kc = k0 + sub * 32;
            if (kc < kend) {
                uint32_t aBase;
                if (kc >= winStart) {
                    aBase = winU + (uint32_t)((kc - winStart) >> 5) * 2048u;
                } else {
                    aBase = sb + (uint32_t)sub * 2048u;
                }
                const uint32_t wB = sb + 4096u + (uint32_t)sub * 8192u;

                uint32_t bh[4], bl[4];
                ldsm4(bh[0], bh[1], bh[2], bh[3], wB + bOff);
                ldsm4(bl[0], bl[1], bl[2], bl[3], wB + 4096u + bOff);

#pragma unroll
                for (int kst = 0; kst < 2; kst++) {
                    const int q = kst * 2 + (lane >> 4);
                    const uint32_t aoff = (uint32_t)(aRow * 64 + ((q ^ aSw) << 4));
                    uint32_t a[4];
                    ldsm4(a[0], a[1], a[2], a[3], aBase + aoff);
                    mma_fp16(cH, a, &bh[kst * 2]);
                    mma_fp16(cL, a, &bl[kst * 2]);
                }
            }
        }
    }
    u = u0 + nIter;

    // ---- epilogue: 4 outputs per warp ----
    const int r0 = wm * 16 + (lane >> 2);
    const int tg = lane & 3;
#pragma unroll
    for (int q = 0; q < 2; q++) {
        int cl = wn * 8 + tg * 2 + q;     // 0..63 window-local col
        int col = wa + cl;
        float bv = bias[col];
        float y0 = fmaxf(cH[q] + cL[q] + bv, 0.f);           // row r0
        float y1 = fmaxf(cH[q + 2] + cL[q + 2] + bv, 0.f);   // row r0+8
        if (outSplit) {
            fp16 h0 = __float2half_rn(y0);
            fp16 h1 = __float2half_rn(y1);
            int kk = col & 31;
            int qp = (kk >> 3) ^ ((r0 >> 1) & 3);
            int eg = ((cta * 32 + (col >> 5)) * 32) * 32;
            int e0 = eg + r0 * 32 + qp * 8 + (kk & 7);
            gA1p[e0] = h0;
            gA1p[e0 + 8 * 32] = h1;
            int ew = ((cl >> 5) * 32 + r0) * 32 + qp * 8 + (kk & 7);
            a1w[ew] = h0;
            a1w[ew + 8 * 32] = h1;
        } else {
            a2w[r0 * 65 + cl] = y0;
            a2w[(r0 + 8) * 65 + cl] = y1;
            gOutF[(size_t)(m0 + r0) * Hh + col] = y0;
            gOutF[(size_t)(m0 + r0 + 8) * Hh + col] = y1;
        }
    }
}

// ---------------- lazy pre0 materialization: cols [msA, msA+64) ----------------
__device__ __forceinline__ void materialize(const float* xs, int cta, int msA,
                                            int idx, fp16* p0w) {
    const int tid = (int)threadIdx.x;
    for (int i = tid; i < 2048; i += NT) {
        int r = i & 31;
        int t = msA + (i >> 5);
        const float* wr = g_W0r + t * Dd;
        float acc = g_b0s[t];
        for (int j = 0; j < idx; j++) acc = fmaf(wr[j], xs[r * 33 + j], acc);
        float y = fmaxf(acc, 0.f);
        fp16 hv = __float2half_rn(y);
        int kk = t & 31;
        int qp = (kk >> 3) ^ ((r >> 1) & 3);
        g_p0p[((cta * 32 + (t >> 5)) * 32 + r) * 32 + qp * 8 + (kk & 7)] = hv;
        int cl = t - msA;
        p0w[((cl >> 5) * 32 + r) * 32 + qp * 8 + (kk & 7)] = hv;
    }
}

// ---------------- finish: mu/ls + x update (row-local) ----------------
__device__ __forceinline__ void finish_phase(const float* __restrict__ z,
                                             const float* __restrict__ bout,
                                             float* __restrict__ x,
                                             const float* a2w, float* xs,
                                             int m0, int idx, int h, int wa) {
    const int wid = (int)threadIdx.x >> 5;
    const int lane = (int)threadIdx.x & 31;
    const float* wmu = g_Wos + (size_t)idx * Hh;
    const float* wls = g_Wos + (size_t)(idx + Dd) * Hh;

#pragma unroll
    for (int rr = 0; rr < 2; rr++) {
        int r = wid * 2 + rr;
        int row = m0 + r;
        float smu = 0.f, sls = 0.f;
        const float* arow = g_a2 + (size_t)row * Hh;
        for (int cc = lane; cc < wa; cc += 32) {
            float av = arow[cc];
            smu = fmaf(av, wmu[cc], smu);
            sls = fmaf(av, wls[cc], sls);
        }
        for (int cc = wa + lane; cc < h; cc += 32) {
            float av = a2w[r * 65 + (cc - wa)];
            smu = fmaf(av, wmu[cc], smu);
            sls = fmaf(av, wls[cc], sls);
        }
#pragma unroll
        for (int o = 16; o; o >>= 1) {
            smu += __shfl_xor_sync(0xffffffffu, smu, o);
            sls += __shfl_xor_sync(0xffffffffu, sls, o);
        }
        float mu = smu + bout[idx];
        float ls = sls + bout[idx + Dd];
        float xi = z[(size_t)row * Dd + idx] * expf(ls) + mu;
        if (lane == 0) {
            x[(size_t)row * Dd + idx] = xi;
            xs[r * 33 + idx] = xi;
        }
    }
}

// ---------------- persistent-per-CTA 32-step loop (no inter-CTA sync) -------
__global__ __launch_bounds__(NT, 1) void step_kernel(const float* __restrict__ z,
                                                     const float* __restrict__ bout,
                                                     float* __restrict__ x) {
    extern __shared__ char smraw[];
    const uint32_t smemBase = smem_u32(smraw);
    const uint32_t mbarBase = smemBase + MBAR_OFF;
    fp16* p0w = (fp16*)(smraw + P0W_OFF);
    fp16* a1w = (fp16*)(smraw + A1W_OFF);
    float* a2w = (float*)(smraw + A2W_OFF);
    float* xs = (float*)(smraw + XS_OFF);
    const int cta = (int)blockIdx.x;
    const int m0 = cta * BMs;

    if (threadIdx.x == 0) {
        for (int s = 0; s < 4; s++) mbar_init(mbarBase + s * 8, 1);
    }
    __syncthreads();

    int u = 0;   // persistent stage-use counter (stage = u&3, parity = (u>>2)&1)

    for (int idx = 0; idx < Dd; idx++) {
        const int h = idx ? (33 * idx + 1) : 0;
        int wa = 0;
        if (idx) {
            const int ms = (idx > 1) ? (33 * (idx - 1) + 1) : 0;
            const int msA = ms & ~31;
            const int kend1 = msA + 64;        // == (h+31)&~31
            materialize(xs, cta, msA, idx, p0w);
            __syncthreads();
            wa = (h - 33) & ~31;
            if (wa > 960) wa = 960;
            const int jw = wa >> 5;
            // layer 1: A = packed p0 (prefix bulk, fresh cols from p0 window)
            gemm_phase(smemBase, mbarBase, u, smem_u32(p0w), msA,
                       m0, wa, kend1,
                       g_p0p + (size_t)cta * 32768,
                       g_Whp + (size_t)jw * 32 * 4096,
                       g_bhs, 1, nullptr, g_a1p, a1w, a2w, cta);
            __syncthreads();
            // layer 2: A = packed a1 (prefix bulk, fresh window in smem)
            gemm_phase(smemBase, mbarBase, u, smem_u32(a1w), wa,
                       m0, wa, wa + 64,
                       g_a1p + (size_t)cta * 32768,
                       g_Whp + (size_t)(31 + jw) * 32 * 4096,
                       g_bhs + Hh, 0, g_a2, nullptr, a1w, a2w, cta);
            __syncthreads();
        }
        finish_phase(z, bout, x, a2w, xs, m0, idx, h, wa);
        __syncthreads();
    }
}

// ---------------- launch ----------------
extern "C" void kernel_launch(void* const* d_in, const int* in_sizes, int n_in,
                              void* d_out, int out_size) {
    const float* z    = (const float*)d_in[0];
    const float* W0   = (const float*)d_in[1];
    const float* b0   = (const float*)d_in[2];
    const float* Wh   = (const float*)d_in[3];
    const float* bh   = (const float*)d_in[4];
    const float* Wout = (const float*)d_in[5];
    const float* bout = (const float*)d_in[6];
    float* x = (float*)d_out;

    static int attrSet = 0;
    if (!attrSet) {
        cudaFuncSetAttribute(step_kernel, cudaFuncAttributeMaxDynamicSharedMemorySize,
                             SMEMB);
        attrSet = 1;
    }

    prep_kernel<<<1024, 256>>>(W0, b0, Wh, bh, Wout);
    step_kernel<<<NCTA, NT, SMEMB>>>(z, bout, x);
}

// round 14
// speedup vs baseline: 6.5313x; 1.0937x over previous
#include <cuda_runtime.h>
#include <cuda_fp16.h>
#include <math.h>
#include <stdint.h>

// Problem constants
#define Dd 32
#define Hh 1024
#define Ll 2
#define Bb 4096
#define BMs 32
#define NCTA 128
#define NT 512

typedef __half fp16;

// ---------------- device scratch (static, no allocation) ----------------
// Packed activation layout: [cta][kchunk 32][row 32][32 k] with 16B-swizzle
// q' = (kk>>3) ^ ((row>>1)&3); element = chunk*1024 + row*32 + q'*8 + (kk&7)
__device__ fp16  g_p0p[NCTA * 32 * 1024];   // packed fp16(relu(pre0))
__device__ fp16  g_a1p[NCTA * 32 * 1024];   // packed layer-1 activations
__device__ float g_a2[Bb * Hh];             // layer-2 activations fp32 (plain)
// Packed weights (single fp16): per (layer l, window jw 0..30, kchunk kc 0..31):
// 4KB tile = 64 rows x 32 k, swizzled like activations. kc-contiguous.
__device__ fp16  g_Whp[2 * 31 * 32 * 2048];
__device__ float g_bhs[Ll * Hh];
__device__ float g_W0r[Hh * Dd];            // masked sorted W0, row-major [t][j]
__device__ float g_b0s[Hh];                 // permuted b0
__device__ float g_Wos[2 * Dd * Hh];

// Degree-sorted permutation. Hidden degree of original unit i is i % 31.
__device__ __forceinline__ int permS(int s) {
    return (s < 34) ? 31 * s : ((s - 1) / 33) + 31 * ((s - 1) % 33);
}
__device__ __forceinline__ int degS(int s) {
    return (s < 34) ? 0 : (s - 1) / 33;
}

// ---------------- weight pre-transform ----------------
__global__ void prep_kernel(const float* __restrict__ W0,
                            const float* __restrict__ b0,
                            const float* __restrict__ Wh,
                            const float* __restrict__ bh,
                            const float* __restrict__ Wout) {
    int stride = gridDim.x * blockDim.x;
    int tid0 = blockIdx.x * blockDim.x + threadIdx.x;

    for (int i = tid0; i < 2 * 31 * 32 * 2048; i += stride) {
        int l = i / 2031616;
        int r1 = i % 2031616;
        int jw = r1 >> 16;
        int r2 = r1 & 65535;
        int kc = r2 >> 11;
        int r3 = r2 & 2047;
        int row = r3 >> 5;
        int kk = r3 & 31;
        int s = jw * 32 + row;
        int t = kc * 32 + kk;
        float v = 0.f;
        if (degS(s) >= degS(t)) v = Wh[l * Hh * Hh + permS(s) * Hh + permS(t)];
        int base = ((l * 31 + jw) * 32 + kc) * 2048;
        int off = row * 32 + (((kk >> 3) ^ ((row >> 1) & 3)) << 3) + (kk & 7);
        g_Whp[base + off] = __float2half_rn(v);
    }
    for (int i = tid0; i < Ll * Hh; i += stride) {
        int l = i >> 10;
        int s = i & (Hh - 1);
        g_bhs[i] = bh[l * Hh + permS(s)];
    }
    for (int i = tid0; i < Hh * Dd; i += stride) {
        int t = i >> 5;
        int j = i & 31;
        g_W0r[i] = (degS(t) >= j) ? W0[permS(t) * Dd + j] : 0.f;
    }
    for (int i = tid0; i < Hh; i += stride) g_b0s[i] = b0[permS(i)];
    for (int i = tid0; i < 2 * Dd * Hh; i += stride) {
        int o = i >> 10;
        int t = i & (Hh - 1);
        g_Wos[i] = (((o & 31) - 1) >= degS(t)) ? Wout[o * Hh + permS(t)] : 0.f;
    }
}

// ---------------- smem layout (bytes) ----------------
// 4 bulk stages @0, each 64-k: {A 4096 | W 8192 (2 x 4KB tiles)} = 12288
// p0 window @49152, a1 window @53248 : 2 chunks x 2048 B each (packed layout)
// a2 window @57344 : [32][65] fp32 (8320 B)
// xs        @65664 : [32][33] fp32 (4224 B)
// mbars     @69888 : 4 x 8 B
#define STGB 12288
#define P0W_OFF 49152
#define A1W_OFF 53248
#define A2W_OFF 57344
#define XS_OFF 65664
#define MBAR_OFF 69888
#define SMEMB 70144

__device__ __forceinline__ uint32_t smem_u32(const void* p) {
    return (uint32_t)__cvta_generic_to_shared(p);
}
__device__ __forceinline__ void cpbulk(uint32_t dst, const void* src,
                                       uint32_t bytes, uint32_t mbar) {
    asm volatile(
        "cp.async.bulk.shared::cta.global.mbarrier::complete_tx::bytes "
        "[%0], [%1], %2, [%3];\n"
        :: "r"(dst), "l"(src), "r"(bytes), "r"(mbar) : "memory");
}
__device__ __forceinline__ void mbar_init(uint32_t a, uint32_t cnt) {
    asm volatile("mbarrier.init.shared.b64 [%0], %1;" :: "r"(a), "r"(cnt) : "memory");
}
__device__ __forceinline__ void mbar_expect(uint32_t a, uint32_t bytes) {
    asm volatile("mbarrier.arrive.expect_tx.shared.b64 _, [%0], %1;"
                 :: "r"(a), "r"(bytes) : "memory");
}
__device__ __forceinline__ void mbar_wait(uint32_t mbar, uint32_t parity) {
    asm volatile(
        "{\n\t"
        ".reg .pred P;\n\t"
        "LW%=:\n\t"
        "mbarrier.try_wait.parity.acquire.cta.shared::cta.b64 P, [%0], %1, 0x989680;\n\t"
        "@P bra LD%=;\n\t"
        "bra LW%=;\n\t"
        "LD%=:\n\t"
        "}"
        :: "r"(mbar), "r"(parity) : "memory");
}
__device__ __forceinline__ void ldsm4(uint32_t& r0, uint32_t& r1, uint32_t& r2,
                                      uint32_t& r3, uint32_t addr) {
    asm volatile("ldmatrix.sync.aligned.m8n8.x4.shared.b16 {%0,%1,%2,%3}, [%4];\n"
                 : "=r"(r0), "=r"(r1), "=r"(r2), "=r"(r3) : "r"(addr));
}
__device__ __forceinline__ void mma_fp16(float c[4], const uint32_t a[4], const uint32_t b[2]) {
    asm volatile(
        "mma.sync.aligned.m16n8k16.row.col.f32.f16.f16.f32 "
        "{%0,%1,%2,%3}, {%4,%5,%6,%7}, {%8,%9}, {%0,%1,%2,%3};\n"
        : "+f"(c[0]), "+f"(c[1]), "+f"(c[2]), "+f"(c[3])
        : "r"(a[0]), "r"(a[1]), "r"(a[2]), "r"(a[3]), "r"(b[0]), "r"(b[1]));
}

// ---------------- window GEMM: out[32 rows, 64 cols @ wa] ----------------
// 64-k stages (2 chunks each): A packed chunks (bulk) or smem window for
// kc >= winStart; W packed 4KB tiles, ONE bulk per stage.
// 4-stage mbarrier ring, fetch-ahead 3, barrier-before-issue.
__device__ __forceinline__ void gemm_phase(
    uint32_t smemBase, uint32_t mbarBase, int& u,
    uint32_t winU, int winStart,
    int m0, int wa, int kend,
    const fp16* __restrict__ A_gp,      // packed A base for this CTA
    const fp16* __restrict__ B_gp,      // packed W base for (layer, window)
    const float* __restrict__ bias, int outSplit,
    float* __restrict__ gOutF, fp16* __restrict__ gA1p,
    fp16* a1w, float* a2w, int cta) {

    const int tid = (int)threadIdx.x;
    const int lane = tid & 31;
    const int wid = tid >> 5;
    const int wm = wid & 1;       // 2 x m16
    const int wn = wid >> 1;      // 8 x n8
    const int lrow = lane & 15;

    float cH[4] = {0.f, 0.f, 0.f, 0.f};
    const int nIter = (kend + 63) >> 6;
    const int u0 = u;

    auto issueStage = [&](int j) {
        int k0 = j * 64;
        int stage = (u0 + j) & 3;
        uint32_t mbar = mbarBase + stage * 8;
        uint32_t dstA = smemBase + (uint32_t)stage * STGB;
        int kA = (winStart - k0) >> 5;           // #A chunks to copy (prefix)
        if (kA < 0) kA = 0; if (kA > 2) kA = 2;
        int rem = (kend - k0) >> 5;
        if (rem > 2) rem = 2;
        if (kA > rem) kA = rem;
        uint32_t bytes = (uint32_t)kA * 2048u + (uint32_t)rem * 4096u;
        mbar_expect(mbar, bytes);
        if (kA)
            cpbulk(dstA, A_gp + (size_t)(k0 >> 5) * 1024, (uint32_t)kA * 2048u, mbar);
        cpbulk(dstA + 4096u, B_gp + (size_t)(k0 >> 5) * 2048, (uint32_t)rem * 4096u, mbar);
    };

    if (tid == 0) {
        for (int j = 0; j < 3 && j < nIter; j++) issueStage(j);
    }

    // ldsm lane addressing (packed/swizzled layout)
    const int aRow = wm * 16 + lrow;
    const int aSw = (aRow >> 1) & 3;
    const int bRow = wn * 8 + (lane & 7);
    const uint32_t bOff = (uint32_t)(bRow * 64 + (((lane >> 3) ^ ((bRow >> 1) & 3)) << 4));

    for (int it = 0; it < nIter; it++) {
        __syncthreads();
        if (tid == 0 && it + 3 < nIter) issueStage(it + 3);
        const int stage = (u0 + it) & 3;
        mbar_wait(mbarBase + stage * 8, (uint32_t)(((u0 + it) >> 2) & 1));

        const uint32_t sb = smemBase + (uint32_t)stage * STGB;
        const int k0 = it * 64;

#pragma unroll
        for (int sub = 0; sub < 2; sub++) {
            const int kc = k0 + sub * 32;
            if (kc < kend) {
                uint32_t aBase;
                if (kc >= winStart) {
                    aBase = winU + (uint32_t)((kc - winStart) >> 5) * 2048u;
                } else {
                    aBase = sb + (uint32_t)sub * 2048u;
                }
                const uint32_t wB = sb + 4096u + (uint32_t)sub * 4096u;

                uint32_t bh[4];
                ldsm4(bh[0], bh[1], bh[2], bh[3], wB + bOff);

#pragma unroll
                for (int kst = 0; kst < 2; kst++) {
                    const int q = kst * 2 + (lane >> 4);
                    const uint32_t aoff = (uint32_t)(aRow * 64 + ((q ^ aSw) << 4));
                    uint32_t a[4];
                    ldsm4(a[0], a[1], a[2], a[3], aBase + aoff);
                    mma_fp16(cH, a, &bh[kst * 2]);
                }
            }
        }
    }
    u = u0 + nIter;

    // ---- epilogue: 4 outputs per warp ----
    const int r0 = wm * 16 + (lane >> 2);
    const int tg = lane & 3;
#pragma unroll
    for (int q = 0; q < 2; q++) {
        int cl = wn * 8 + tg * 2 + q;     // 0..63 window-local col
        int col = wa + cl;
        float bv = bias[col];
        float y0 = fmaxf(cH[q] + bv, 0.f);       // row r0
        float y1 = fmaxf(cH[q + 2] + bv, 0.f);   // row r0+8
        if (outSplit) {
            fp16 h0 = __float2half_rn(y0);
            fp16 h1 = __float2half_rn(y1);
            int kk = col & 31;
            int qp = (kk >> 3) ^ ((r0 >> 1) & 3);
            int eg = ((cta * 32 + (col >> 5)) * 32) * 32;
            int e0 = eg + r0 * 32 + qp * 8 + (kk & 7);
            gA1p[e0] = h0;
            gA1p[e0 + 8 * 32] = h1;
            int ew = ((cl >> 5) * 32 + r0) * 32 + qp * 8 + (kk & 7);
            a1w[ew] = h0;
            a1w[ew + 8 * 32] = h1;
        } else {
            a2w[r0 * 65 + cl] = y0;
            a2w[(r0 + 8) * 65 + cl] = y1;
            gOutF[(size_t)(m0 + r0) * Hh + col] = y0;
            gOutF[(size_t)(m0 + r0 + 8) * Hh + col] = y1;
        }
    }
}

// ---------------- lazy pre0 materialization: cols [msA, msA+64) ----------------
__device__ __forceinline__ void materialize(const float* xs, int cta, int msA,
                                            int idx, fp16* p0w) {
    const int tid = (int)threadIdx.x;
    for (int i = tid; i < 2048; i += NT) {
        int r = i & 31;
        int t = msA + (i >> 5);
        const float* wr = g_W0r + t * Dd;
        float acc = g_b0s[t];
        for (int j = 0; j < idx; j++) acc = fmaf(wr[j], xs[r * 33 + j], acc);
        float y = fmaxf(acc, 0.f);
        fp16 hv = __float2half_rn(y);
        int kk = t & 31;
        int qp = (kk >> 3) ^ ((r >> 1) & 3);
        g_p0p[((cta * 32 + (t >> 5)) * 32 + r) * 32 + qp * 8 + (kk & 7)] = hv;
        int cl = t - msA;
        p0w[((cl >> 5) * 32 + r) * 32 + qp * 8 + (kk & 7)] = hv;
    }
}

// ---------------- finish: mu/ls + x update (row-local) ----------------
__device__ __forceinline__ void finish_phase(const float* __restrict__ z,
                                             const float* __restrict__ bout,
                                             float* __restrict__ x,
                                             const float* a2w, float* xs,
                                             int m0, int idx, int h, int wa) {
    const int wid = (int)threadIdx.x >> 5;
    const int lane = (int)threadIdx.x & 31;
    const float* wmu = g_Wos + (size_t)idx * Hh;
    const float* wls = g_Wos + (size_t)(idx + Dd) * Hh;

#pragma unroll
    for (int rr = 0; rr < 2; rr++) {
        int r = wid * 2 + rr;
        int row = m0 + r;
        float smu = 0.f, sls = 0.f;
        const float* arow = g_a2 + (size_t)row * Hh;
        for (int cc = lane; cc < wa; cc += 32) {
            float av = arow[cc];
            smu = fmaf(av, wmu[cc], smu);
            sls = fmaf(av, wls[cc], sls);
        }
        for (int cc = wa + lane; cc < h; cc += 32) {
            float av = a2w[r * 65 + (cc - wa)];
            smu = fmaf(av, wmu[cc], smu);
            sls = fmaf(av, wls[cc], sls);
        }
#pragma unroll
        for (int o = 16; o; o >>= 1) {
            smu += __shfl_xor_sync(0xffffffffu, smu, o);
            sls += __shfl_xor_sync(0xffffffffu, sls, o);
        }
        float mu = smu + bout[idx];
        float ls = sls + bout[idx + Dd];
        float xi = z[(size_t)row * Dd + idx] * expf(ls) + mu;
        if (lane == 0) {
            x[(size_t)row * Dd + idx] = xi;
            xs[r * 33 + idx] = xi;
        }
    }
}

// ---------------- persistent-per-CTA 32-step loop (no inter-CTA sync) -------
__global__ __launch_bounds__(NT, 1) void step_kernel(const float* __restrict__ z,
                                                     const float* __restrict__ bout,
                                                     float* __restrict__ x) {
    extern __shared__ char smraw[];
    const uint32_t smemBase = smem_u32(smraw);
    const uint32_t mbarBase = smemBase + MBAR_OFF;
    fp16* p0w = (fp16*)(smraw + P0W_OFF);
    fp16* a1w = (fp16*)(smraw + A1W_OFF);
    float* a2w = (float*)(smraw + A2W_OFF);
    float* xs = (float*)(smraw + XS_OFF);
    const int cta = (int)blockIdx.x;
    const int m0 = cta * BMs;

    if (threadIdx.x == 0) {
        for (int s = 0; s < 4; s++) mbar_init(mbarBase + s * 8, 1);
    }
    __syncthreads();

    int u = 0;   // persistent stage-use counter (stage = u&3, parity = (u>>2)&1)

    for (int idx = 0; idx < Dd; idx++) {
        const int h = idx ? (33 * idx + 1) : 0;
        int wa = 0;
        if (idx) {
            const int ms = (idx > 1) ? (33 * (idx - 1) + 1) : 0;
            const int msA = ms & ~31;
            const int kend1 = msA + 64;        // == (h+31)&~31
            materialize(xs, cta, msA, idx, p0w);
            __syncthreads();
            wa = (h - 33) & ~31;
            if (wa > 960) wa = 960;
            const int jw = wa >> 5;
            // layer 1: A = packed p0 (prefix bulk, fresh cols from p0 window)
            gemm_phase(smemBase, mbarBase, u, smem_u32(p0w), msA,
                       m0, wa, kend1,
                       g_p0p + (size_t)cta * 32768,
                       g_Whp + (size_t)jw * 32 * 2048,
                       g_bhs, 1, nullptr, g_a1p, a1w, a2w, cta);
            __syncthreads();
            // layer 2: A = packed a1 (prefix bulk, fresh window in smem)
            gemm_phase(smemBase, mbarBase, u, smem_u32(a1w), wa,
                       m0, wa, wa + 64,
                       g_a1p + (size_t)cta * 32768,
                       g_Whp + (size_t)(31 + jw) * 32 * 2048,
                       g_bhs + Hh, 0, g_a2, nullptr, a1w, a2w, cta);
            __syncthreads();
        }
        finish_phase(z, bout, x, a2w, xs, m0, idx, h, wa);
        __syncthreads();
    }
}

// ---------------- launch ----------------
extern "C" void kernel_launch(void* const* d_in, const int* in_sizes, int n_in,
                              void* d_out, int out_size) {
    const float* z    = (const float*)d_in[0];
    const float* W0   = (const float*)d_in[1];
    const float* b0   = (const float*)d_in[2];
    const float* Wh   = (const float*)d_in[3];
    const float* bh   = (const float*)d_in[4];
    const float* Wout = (const float*)d_in[5];
    const float* bout = (const float*)d_in[6];
    float* x = (float*)d_out;

    static int attrSet = 0;
    if (!attrSet) {
        cudaFuncSetAttribute(step_kernel, cudaFuncAttributeMaxDynamicSharedMemorySize,
                             SMEMB);
        attrSet = 1;
    }

    prep_kernel<<<1024, 256>>>(W0, b0, Wh, bh, Wout);
    step_kernel<<<NCTA, NT, SMEMB>>>(z, bout, x);
}

// round 15
// speedup vs baseline: 7.0867x; 1.0850x over previous
#include <cuda_runtime.h>
#include <cuda_fp16.h>
#include <math.h>
#include <stdint.h>

// Problem constants
#define Dd 32
#define Hh 1024
#define Ll 2
#define Bb 4096
#define BMs 32
#define NCTA 128
#define NT 512

typedef __half fp16;

// ---------------- device scratch (static, no allocation) ----------------
// Packed activation layout: [cta][kchunk 32][row 32][32 k] with 16B-swizzle
// q' = (kk>>3) ^ ((row>>1)&3); element = chunk*1024 + row*32 + q'*8 + (kk&7)
__device__ fp16  g_p0p[NCTA * 32 * 1024];   // packed fp16(relu(pre0))
__device__ fp16  g_a1p[NCTA * 32 * 1024];   // packed layer-1 activations
__device__ float g_a2[Bb * Hh];             // layer-2 activations fp32 (plain)
// Packed weights (single fp16): per (layer l, window jw 0..30, kchunk kc 0..31):
// 4KB tile = 64 rows x 32 k, swizzled like activations. kc-contiguous.
__device__ fp16  g_Whp[2 * 31 * 32 * 2048];
__device__ float g_bhs[Ll * Hh];
__device__ float g_W0r[Hh * Dd];            // masked sorted W0, row-major [t][j]
__device__ float g_b0s[Hh];                 // permuted b0
__device__ float g_Wos[2 * Dd * Hh];

// Degree-sorted permutation. Hidden degree of original unit i is i % 31.
__device__ __forceinline__ int permS(int s) {
    return (s < 34) ? 31 * s : ((s - 1) / 33) + 31 * ((s - 1) % 33);
}
__device__ __forceinline__ int degS(int s) {
    return (s < 34) ? 0 : (s - 1) / 33;
}

// ---------------- weight pre-transform ----------------
__global__ void prep_kernel(const float* __restrict__ W0,
                            const float* __restrict__ b0,
                            const float* __restrict__ Wh,
                            const float* __restrict__ bh,
                            const float* __restrict__ Wout) {
    int stride = gridDim.x * blockDim.x;
    int tid0 = blockIdx.x * blockDim.x + threadIdx.x;

    for (int i = tid0; i < 2 * 31 * 32 * 2048; i += stride) {
        int l = i / 2031616;
        int r1 = i % 2031616;
        int jw = r1 >> 16;
        int r2 = r1 & 65535;
        int kc = r2 >> 11;
        int r3 = r2 & 2047;
        int row = r3 >> 5;
        int kk = r3 & 31;
        int s = jw * 32 + row;
        int t = kc * 32 + kk;
        float v = 0.f;
        if (degS(s) >= degS(t)) v = Wh[l * Hh * Hh + permS(s) * Hh + permS(t)];
        int base = ((l * 31 + jw) * 32 + kc) * 2048;
        int off = row * 32 + (((kk >> 3) ^ ((row >> 1) & 3)) << 3) + (kk & 7);
        g_Whp[base + off] = __float2half_rn(v);
    }
    for (int i = tid0; i < Ll * Hh; i += stride) {
        int l = i >> 10;
        int s = i & (Hh - 1);
        g_bhs[i] = bh[l * Hh + permS(s)];
    }
    for (int i = tid0; i < Hh * Dd; i += stride) {
        int t = i >> 5;
        int j = i & 31;
        g_W0r[i] = (degS(t) >= j) ? W0[permS(t) * Dd + j] : 0.f;
    }
    for (int i = tid0; i < Hh; i += stride) g_b0s[i] = b0[permS(i)];
    for (int i = tid0; i < 2 * Dd * Hh; i += stride) {
        int o = i >> 10;
        int t = i & (Hh - 1);
        g_Wos[i] = (((o & 31) - 1) >= degS(t)) ? Wout[o * Hh + permS(t)] : 0.f;
    }
}

// ---------------- smem layout (bytes) ----------------
// 4 bulk stages @0, each 128-k (4 chunks): {A 8192 | W 16384} = 24576
// p0 window @98304, a1 window @102400 : 2 chunks x 2048 B each
// a2 window @106496 : [32][65] fp32 (8320 B)
// xs        @114816 : [32][33] fp32 (4224 B)
// mbars     @119040 : 4 x 8 B
#define STGB 24576
#define P0W_OFF 98304
#define A1W_OFF 102400
#define A2W_OFF 106496
#define XS_OFF 114816
#define MBAR_OFF 119040
#define SMEMB 119296

__device__ __forceinline__ uint32_t smem_u32(const void* p) {
    return (uint32_t)__cvta_generic_to_shared(p);
}
__device__ __forceinline__ void cpbulk(uint32_t dst, const void* src,
                                       uint32_t bytes, uint32_t mbar) {
    asm volatile(
        "cp.async.bulk.shared::cta.global.mbarrier::complete_tx::bytes "
        "[%0], [%1], %2, [%3];\n"
        :: "r"(dst), "l"(src), "r"(bytes), "r"(mbar) : "memory");
}
__device__ __forceinline__ void mbar_init(uint32_t a, uint32_t cnt) {
    asm volatile("mbarrier.init.shared.b64 [%0], %1;" :: "r"(a), "r"(cnt) : "memory");
}
__device__ __forceinline__ void mbar_expect(uint32_t a, uint32_t bytes) {
    asm volatile("mbarrier.arrive.expect_tx.shared.b64 _, [%0], %1;"
                 :: "r"(a), "r"(bytes) : "memory");
}
__device__ __forceinline__ void mbar_wait(uint32_t mbar, uint32_t parity) {
    asm volatile(
        "{\n\t"
        ".reg .pred P;\n\t"
        "LW%=:\n\t"
        "mbarrier.try_wait.parity.acquire.cta.shared::cta.b64 P, [%0], %1, 0x989680;\n\t"
        "@P bra LD%=;\n\t"
        "bra LW%=;\n\t"
        "LD%=:\n\t"
        "}"
        :: "r"(mbar), "r"(parity) : "memory");
}
__device__ __forceinline__ void ldsm4(uint32_t& r0, uint32_t& r1, uint32_t& r2,
                                      uint32_t& r3, uint32_t addr) {
    asm volatile("ldmatrix.sync.aligned.m8n8.x4.shared.b16 {%0,%1,%2,%3}, [%4];\n"
                 : "=r"(r0), "=r"(r1), "=r"(r2), "=r"(r3) : "r"(addr));
}
__device__ __forceinline__ void mma_fp16(float c[4], const uint32_t a[4], const uint32_t b[2]) {
    asm volatile(
        "mma.sync.aligned.m16n8k16.row.col.f32.f16.f16.f32 "
        "{%0,%1,%2,%3}, {%4,%5,%6,%7}, {%8,%9}, {%0,%1,%2,%3};\n"
        : "+f"(c[0]), "+f"(c[1]), "+f"(c[2]), "+f"(c[3])
        : "r"(a[0]), "r"(a[1]), "r"(a[2]), "r"(a[3]), "r"(b[0]), "r"(b[1]));
}

// ---------------- window GEMM: out[32 rows, 64 cols @ wa] ----------------
// 128-k stages (4 chunks each): A packed chunks (bulk) or smem window for
// kc >= winStart; W packed 4KB tiles, ONE bulk per stage.
// 4-stage mbarrier ring, fetch-ahead 3, barrier-before-issue.
// Two accumulator chains (even/odd sub-chunk) halve the MMA dependency depth.
__device__ __forceinline__ void gemm_phase(
    uint32_t smemBase, uint32_t mbarBase, int& u,
    uint32_t winU, int winStart,
    int m0, int wa, int kend,
    const fp16* __restrict__ A_gp,      // packed A base for this CTA
    const fp16* __restrict__ B_gp,      // packed W base for (layer, window)
    const float* __restrict__ bias, int outSplit,
    float* __restrict__ gOutF, fp16* __restrict__ gA1p,
    fp16* a1w, float* a2w, int cta) {

    const int tid = (int)threadIdx.x;
    const int lane = tid & 31;
    const int wid = tid >> 5;
    const int wm = wid & 1;       // 2 x m16
    const int wn = wid >> 1;      // 8 x n8
    const int lrow = lane & 15;

    float c0[4] = {0.f, 0.f, 0.f, 0.f};
    float c1[4] = {0.f, 0.f, 0.f, 0.f};
    const int nIter = (kend + 127) >> 7;
    const int u0 = u;

    auto issueStage = [&](int j) {
        int k0 = j * 128;
        int stage = (u0 + j) & 3;
        uint32_t mbar = mbarBase + stage * 8;
        uint32_t dstA = smemBase + (uint32_t)stage * STGB;
        int kA = (winStart - k0) >> 5;           // #A chunks to copy (prefix)
        if (kA < 0) kA = 0; if (kA > 4) kA = 4;
        int rem = (kend - k0) >> 5;
        if (rem > 4) rem = 4;
        if (kA > rem) kA = rem;
        uint32_t bytes = (uint32_t)kA * 2048u + (uint32_t)rem * 4096u;
        mbar_expect(mbar, bytes);
        if (kA)
            cpbulk(dstA, A_gp + (size_t)(k0 >> 5) * 1024, (uint32_t)kA * 2048u, mbar);
        cpbulk(dstA + 8192u, B_gp + (size_t)(k0 >> 5) * 2048, (uint32_t)rem * 4096u, mbar);
    };

    if (tid == 0) {
        for (int j = 0; j < 3 && j < nIter; j++) issueStage(j);
    }

    // ldsm lane addressing (packed/swizzled layout)
    const int aRow = wm * 16 + lrow;
    const int aSw = (aRow >> 1) & 3;
    const int bRow = wn * 8 + (lane & 7);
    const uint32_t bOff = (uint32_t)(bRow * 64 + (((lane >> 3) ^ ((bRow >> 1) & 3)) << 4));

    for (int it = 0; it < nIter; it++) {
        __syncthreads();
        if (tid == 0 && it + 3 < nIter) issueStage(it + 3);
        const int stage = (u0 + it) & 3;
        mbar_wait(mbarBase + stage * 8, (uint32_t)(((u0 + it) >> 2) & 1));

        const uint32_t sb = smemBase + (uint32_t)stage * STGB;
        const int k0 = it * 128;

#pragma unroll
        for (int sub = 0; sub < 4; sub++) {
            const int kc = k0 + sub * 32;
            if (kc < kend) {
                uint32_t aBase;
                if (kc >= winStart) {
                    aBase = winU + (uint32_t)((kc - winStart) >> 5) * 2048u;
                } else {
                    aBase = sb + (uint32_t)sub * 2048u;
                }
                const uint32_t wB = sb + 8192u + (uint32_t)sub * 4096u;

                uint32_t bh[4];
                ldsm4(bh[0], bh[1], bh[2], bh[3], wB + bOff);
                float* acc = (sub & 1) ? c1 : c0;

#pragma unroll
                for (int kst = 0; kst < 2; kst++) {
                    const int q = kst * 2 + (lane >> 4);
                    const uint32_t aoff = (uint32_t)(aRow * 64 + ((q ^ aSw) << 4));
                    uint32_t a[4];
                    ldsm4(a[0], a[1], a[2], a[3], aBase + aoff);
                    mma_fp16(acc, a, &bh[kst * 2]);
                }
            }
        }
    }
    u = u0 + nIter;

    // ---- epilogue: 4 outputs per warp ----
    const int r0 = wm * 16 + (lane >> 2);
    const int tg = lane & 3;
#pragma unroll
    for (int q = 0; q < 2; q++) {
        int cl = wn * 8 + tg * 2 + q;     // 0..63 window-local col
        int col = wa + cl;
        float bv = bias[col];
        float y0 = fmaxf(c0[q] + c1[q] + bv, 0.f);           // row r0
        float y1 = fmaxf(c0[q + 2] + c1[q + 2] + bv, 0.f);   // row r0+8
        if (outSplit) {
            fp16 h0 = __float2half_rn(y0);
            fp16 h1 = __float2half_rn(y1);
            int kk = col & 31;
            int qp = (kk >> 3) ^ ((r0 >> 1) & 3);
            int eg = ((cta * 32 + (col >> 5)) * 32) * 32;
            int e0 = eg + r0 * 32 + qp * 8 + (kk & 7);
            gA1p[e0] = h0;
            gA1p[e0 + 8 * 32] = h1;
            int ew = ((cl >> 5) * 32 + r0) * 32 + qp * 8 + (kk & 7);
            a1w[ew] = h0;
            a1w[ew + 8 * 32] = h1;
        } else {
            a2w[r0 * 65 + cl] = y0;
            a2w[(r0 + 8) * 65 + cl] = y1;
            gOutF[(size_t)(m0 + r0) * Hh + col] = y0;
            gOutF[(size_t)(m0 + r0 + 8) * Hh + col] = y1;
        }
    }
}

// ---------------- lazy pre0 materialization: cols [msA, msA+64) ----------------
__device__ __forceinline__ void materialize(const float* xs, int cta, int msA,
                                            int idx, fp16* p0w) {
    const int tid = (int)threadIdx.x;
    for (int i = tid; i < 2048; i += NT) {
        int r = i & 31;
        int t = msA + (i >> 5);
        const float* wr = g_W0r + t * Dd;
        float acc = g_b0s[t];
        for (int j = 0; j < idx; j++) acc = fmaf(wr[j], xs[r * 33 + j], acc);
        float y = fmaxf(acc, 0.f);
        fp16 hv = __float2half_rn(y);
        int kk = t & 31;
        int qp = (kk >> 3) ^ ((r >> 1) & 3);
        g_p0p[((cta * 32 + (t >> 5)) * 32 + r) * 32 + qp * 8 + (kk & 7)] = hv;
        int cl = t - msA;
        p0w[((cl >> 5) * 32 + r) * 32 + qp * 8 + (kk & 7)] = hv;
    }
}

// ---------------- finish: mu/ls + x update (row-local) ----------------
__device__ __forceinline__ void finish_phase(const float* __restrict__ z,
                                             const float* __restrict__ bout,
                                             float* __restrict__ x,
                                             const float* a2w, float* xs,
                                             int m0, int idx, int h, int wa) {
    const int wid = (int)threadIdx.x >> 5;
    const int lane = (int)threadIdx.x & 31;
    const float* wmu = g_Wos + (size_t)idx * Hh;
    const float* wls = g_Wos + (size_t)(idx + Dd) * Hh;

#pragma unroll
    for (int rr = 0; rr < 2; rr++) {
        int r = wid * 2 + rr;
        int row = m0 + r;
        float smu = 0.f, sls = 0.f;
        const float* arow = g_a2 + (size_t)row * Hh;
        for (int cc = lane; cc < wa; cc += 32) {
            float av = arow[cc];
            smu = fmaf(av, wmu[cc], smu);
            sls = fmaf(av, wls[cc], sls);
        }
        for (int cc = wa + lane; cc < h; cc += 32) {
            float av = a2w[r * 65 + (cc - wa)];
            smu = fmaf(av, wmu[cc], smu);
            sls = fmaf(av, wls[cc], sls);
        }
#pragma unroll
        for (int o = 16; o; o >>= 1) {
            smu += __shfl_xor_sync(0xffffffffu, smu, o);
            sls += __shfl_xor_sync(0xffffffffu, sls, o);
        }
        float mu = smu + bout[idx];
        float ls = sls + bout[idx + Dd];
        float xi = z[(size_t)row * Dd + idx] * expf(ls) + mu;
        if (lane == 0) {
            x[(size_t)row * Dd + idx] = xi;
            xs[r * 33 + idx] = xi;
        }
    }
}

// ---------------- persistent-per-CTA 32-step loop (no inter-CTA sync) -------
__global__ __launch_bounds__(NT, 1) void step_kernel(const float* __restrict__ z,
                                                     const float* __restrict__ bout,
                                                     float* __restrict__ x) {
    extern __shared__ char smraw[];
    const uint32_t smemBase = smem_u32(smraw);
    const uint32_t mbarBase = smemBase + MBAR_OFF;
    fp16* p0w = (fp16*)(smraw + P0W_OFF);
    fp16* a1w = (fp16*)(smraw + A1W_OFF);
    float* a2w = (float*)(smraw + A2W_OFF);
    float* xs = (float*)(smraw + XS_OFF);
    const int cta = (int)blockIdx.x;
    const int m0 = cta * BMs;

    if (threadIdx.x == 0) {
        for (int s = 0; s < 4; s++) mbar_init(mbarBase + s * 8, 1);
    }
    __syncthreads();

    int u = 0;   // persistent stage-use counter (stage = u&3, parity = (u>>2)&1)

    for (int idx = 0; idx < Dd; idx++) {
        const int h = idx ? (33 * idx + 1) : 0;
        int wa = 0;
        if (idx) {
            const int ms = (idx > 1) ? (33 * (idx - 1) + 1) : 0;
            const int msA = ms & ~31;
            const int kend1 = msA + 64;        // == (h+31)&~31
            materialize(xs, cta, msA, idx, p0w);
            __syncthreads();
            wa = (h - 33) & ~31;
            if (wa > 960) wa = 960;
            const int jw = wa >> 5;
            // layer 1: A = packed p0 (prefix bulk, fresh cols from p0 window)
            gemm_phase(smemBase, mbarBase, u, smem_u32(p0w), msA,
                       m0, wa, kend1,
                       g_p0p + (size_t)cta * 32768,
                       g_Whp + (size_t)jw * 32 * 2048,
                       g_bhs, 1, nullptr, g_a1p, a1w, a2w, cta);
            __syncthreads();
            // layer 2: A = packed a1 (prefix bulk, fresh window in smem)
            gemm_phase(smemBase, mbarBase, u, smem_u32(a1w), wa,
                       m0, wa, wa + 64,
                       g_a1p + (size_t)cta * 32768,
                       g_Whp + (size_t)(31 + jw) * 32 * 2048,
                       g_bhs + Hh, 0, g_a2, nullptr, a1w, a2w, cta);
            __syncthreads();
        }
        finish_phase(z, bout, x, a2w, xs, m0, idx, h, wa);
        __syncthreads();
    }
}

// ---------------- launch ----------------
extern "C" void kernel_launch(void* const* d_in, const int* in_sizes, int n_in,
                              void* d_out, int out_size) {
    const float* z    = (const float*)d_in[0];
    const float* W0   = (const float*)d_in[1];
    const float* b0   = (const float*)d_in[2];
    const float* Wh   = (const float*)d_in[3];
    const float* bh   = (const float*)d_in[4];
    const float* Wout = (const float*)d_in[5];
    const float* bout = (const float*)d_in[6];
    float* x = (float*)d_out;

    static int attrSet = 0;
    if (!attrSet) {
        cudaFuncSetAttribute(step_kernel, cudaFuncAttributeMaxDynamicSharedMemorySize,
                             SMEMB);
        attrSet = 1;
    }

    prep_kernel<<<1024, 256>>>(W0, b0, Wh, bh, Wout);
    step_kernel<<<NCTA, NT, SMEMB>>>(z, bout, x);
}